// round 10
// baseline (speedup 1.0000x reference)
#include <cuda_runtime.h>
#include <cstdint>
#include <cstddef>

// ============================================================
// Problem dims (fixed)
// ============================================================
#define MROWS 8192
#define NDIM  4096
#define KDIM  4096
#define KGROUPS 32                   // 4096 / 128 quant groups per row

// GEMM tiling: CTA 128x128, 8 warps (2 M x 4 N), warp tile 64x32
#define TM 128
#define TN 128
#define KB 128                       // K int8 per stage = ONE quant group
#define NKB (KDIM / KB)              // 32
#define NSTAGES 3                    // 3 stages -> 112 KB/CTA -> 2 CTAs/SM
#define A_BYTES (TM * 128)           // 16384
#define B_BYTES (TN * 128)           // 16384
#define STAGE_BYTES (A_BYTES + B_BYTES)            // 32768
#define SW_BYTES (KGROUPS * TN * 4)                // 16384 group scales in SMEM
#define GEMM_SMEM (SW_BYTES + NSTAGES * STAGE_BYTES)   // 114688

#define THREADS 256                  // 8 warps; 2 CTAs/SM for barrier overlap

// int bit pattern of 12582912.0f (2^23 + 2^22): magic bias for exact int->float
#define MAGIC_I 0x4B400000
#define MAGIC_F 12582912.0f

// ============================================================
// Scratch (static __device__ — no runtime allocation)
// ============================================================
__device__ signed char g_XQ[(size_t)MROWS * KDIM];   // 32 MB: qx int8 (exact)
__device__ signed char g_WQ[(size_t)NDIM * KDIM];    // 16 MB: wq = (q - z) in [0,15]
__device__ float g_SX[MROWS];                        // activation scale per row
__device__ float g_ZX[MROWS];                        // activation zero per row
__device__ float g_WS[(size_t)NDIM * KGROUPS];       // weight group scale sw[n][g]
__device__ float g_WGS[(size_t)NDIM * KGROUPS];      // sw[n][g] * sum_{k in g} wq
__device__ float g_WSUM[NDIM];                       // sum_k w_deq[n][k]

// ============================================================
// PTX helpers (sm_100 baseline ISA — no 'a'-suffix features)
// ============================================================
__device__ __forceinline__ uint32_t smem_u32(const void* p) {
    uint32_t a;
    asm("{ .reg .u64 t; cvta.to.shared.u64 t, %1; cvt.u32.u64 %0, t; }" : "=r"(a) : "l"(p));
    return a;
}

#define CP16(smem_addr, gptr) \
    asm volatile("cp.async.cg.shared.global [%0], [%1], 16;" :: "r"(smem_addr), "l"(gptr) : "memory")
#define CP_COMMIT()  asm volatile("cp.async.commit_group;" ::: "memory")
#define CP_WAIT1()   asm volatile("cp.async.wait_group 1;" ::: "memory")
#define CP_WAIT0()   asm volatile("cp.async.wait_group 0;" ::: "memory")

#define LDSM_X4(r0, r1, r2, r3, addr)                                        \
    asm volatile("ldmatrix.sync.aligned.m8n8.x4.shared.b16 {%0,%1,%2,%3}, [%4];" \
                 : "=r"(r0), "=r"(r1), "=r"(r2), "=r"(r3) : "r"(addr))

#define MMAS8(c, a, b0, b1)                                                  \
    asm volatile("mma.sync.aligned.m16n8k32.row.col.s32.s8.s8.s32 "          \
                 "{%0,%1,%2,%3}, {%4,%5,%6,%7}, {%8,%9}, {%0,%1,%2,%3};"     \
                 : "+r"((c)[0]), "+r"((c)[1]), "+r"((c)[2]), "+r"((c)[3])    \
                 : "r"((a)[0]), "r"((a)[1]), "r"((a)[2]), "r"((a)[3]),       \
                   "r"((b0)), "r"((b1)))

// Stage load: A rows {r0,+32,+64,+96}, B rows same; one 16B chunk/row/thread.
#define LOAD_STAGE(kb)                                                        \
    do {                                                                      \
        const uint32_t so_ = (uint32_t)((kb) % NSTAGES) * STAGE_BYTES;        \
        const signed char* pA = gA + (size_t)(kb) * 128;                      \
        const signed char* pB = gB + (size_t)(kb) * 128;                      \
        CP16(smA + so_,            pA);                                       \
        CP16(smA + so_ + 32 * 128, pA + (size_t)32 * KDIM);                   \
        CP16(smA + so_ + 64 * 128, pA + (size_t)64 * KDIM);                   \
        CP16(smA + so_ + 96 * 128, pA + (size_t)96 * KDIM);                   \
        CP16(smB + so_,            pB);                                       \
        CP16(smB + so_ + 32 * 128, pB + (size_t)32 * KDIM);                   \
        CP16(smB + so_ + 64 * 128, pB + (size_t)64 * KDIM);                   \
        CP16(smB + so_ + 96 * 128, pB + (size_t)96 * KDIM);                   \
        CP_COMMIT();                                                          \
    } while (0)

// ============================================================
// Kernel 1: weight group quant (gs=128, nbit=4, asym) -> int8 wq + scales
// ============================================================
__global__ void __launch_bounds__(256) w_quant_kernel(const float* __restrict__ w) {
    int g    = blockIdx.x * 8 + (threadIdx.x >> 5);   // group id = n*32 + gk
    int lane = threadIdx.x & 31;
    const float4 f = ((const float4*)(w + (size_t)g * 128))[lane];

    float v[4] = {f.x, f.y, f.z, f.w};
    float mn = fminf(fminf(v[0], v[1]), fminf(v[2], v[3]));
    float mx = fmaxf(fmaxf(v[0], v[1]), fmaxf(v[2], v[3]));
#pragma unroll
    for (int off = 16; off > 0; off >>= 1) {
        mn = fminf(mn, __shfl_xor_sync(0xffffffffu, mn, off));
        mx = fmaxf(mx, __shfl_xor_sync(0xffffffffu, mx, off));
    }
    float sc = __fdiv_rn(mx - mn, 15.0f);
    if (!(sc > 0.0f)) sc = 1.0f;
    float z = -8.0f - rintf(__fdiv_rn(mn, sc));

    float gsum = 0.0f;
    signed char o[4];
#pragma unroll
    for (int j = 0; j < 4; j++) {
        float q = rintf(__fdiv_rn(v[j], sc)) + z;
        q = fminf(fmaxf(q, -8.0f), 7.0f);
        float wq = q - z;                 // exact small integer in [0,15]
        gsum += wq;
        o[j] = (signed char)__float2int_rn(wq);
    }
    ((char4*)(g_WQ + (size_t)g * 128))[lane] = make_char4(o[0], o[1], o[2], o[3]);
#pragma unroll
    for (int off = 16; off > 0; off >>= 1)
        gsum += __shfl_xor_sync(0xffffffffu, gsum, off);
    if (lane == 0) {
        g_WS[g]  = sc;
        g_WGS[g] = sc * gsum;
    }
}

// ============================================================
// Kernel 1b: WSUM[n] = sum_g g_WGS[n*32+g]
// ============================================================
__global__ void __launch_bounds__(256) wsum_kernel() {
    int n    = blockIdx.x * 8 + (threadIdx.x >> 5);
    int lane = threadIdx.x & 31;
    float v = g_WGS[(size_t)n * KGROUPS + lane];
#pragma unroll
    for (int off = 16; off > 0; off >>= 1)
        v += __shfl_xor_sync(0xffffffffu, v, off);
    if (lane == 0) g_WSUM[n] = v;
}

// ============================================================
// Kernel 2: activation dynamic per-row int8 quant -> qx int8, sx, zx
// ============================================================
__global__ void __launch_bounds__(256) act_quant_kernel(const float* __restrict__ x) {
    int row = blockIdx.x;
    int tid = threadIdx.x;
    const float4* xr4 = (const float4*)(x + (size_t)row * KDIM);

    float vals[16];
    float mn = 3.4e38f, mx = -3.4e38f;
#pragma unroll
    for (int j = 0; j < 4; j++) {
        float4 f = xr4[tid + j * 256];
        vals[4 * j + 0] = f.x; vals[4 * j + 1] = f.y;
        vals[4 * j + 2] = f.z; vals[4 * j + 3] = f.w;
        mn = fminf(mn, fminf(fminf(f.x, f.y), fminf(f.z, f.w)));
        mx = fmaxf(mx, fmaxf(fmaxf(f.x, f.y), fmaxf(f.z, f.w)));
    }
#pragma unroll
    for (int off = 16; off > 0; off >>= 1) {
        mn = fminf(mn, __shfl_xor_sync(0xffffffffu, mn, off));
        mx = fmaxf(mx, __shfl_xor_sync(0xffffffffu, mx, off));
    }
    __shared__ float smin[8], smax[8];
    __shared__ float s_sc, s_z;
    if ((tid & 31) == 0) { smin[tid >> 5] = mn; smax[tid >> 5] = mx; }
    __syncthreads();
    if (tid == 0) {
        float rmn = smin[0], rmx = smax[0];
#pragma unroll
        for (int i = 1; i < 8; i++) { rmn = fminf(rmn, smin[i]); rmx = fmaxf(rmx, smax[i]); }
        float sc = __fdiv_rn(rmx - rmn, 255.0f);
        if (!(sc > 0.0f)) sc = 1.0f;
        float z = -128.0f - rintf(__fdiv_rn(rmn, sc));
        s_sc = sc; s_z = z;
        g_SX[row] = sc;
        g_ZX[row] = z;
    }
    __syncthreads();
    float sc = s_sc, z = s_z;
    char4* outp4 = (char4*)(g_XQ + (size_t)row * KDIM);
#pragma unroll
    for (int j = 0; j < 4; j++) {
        signed char o[4];
#pragma unroll
        for (int e = 0; e < 4; e++) {
            float q = rintf(__fdiv_rn(vals[4 * j + e], sc)) + z;
            q = fminf(fmaxf(q, -128.0f), 127.0f);
            o[e] = (signed char)__float2int_rn(q);
        }
        outp4[tid + j * 256] = make_char4(o[0], o[1], o[2], o[3]);
    }
}

// ============================================================
// Kernel 3: int8 IMMA GEMM (magic-bias group fold, exact)
// CTA 128x128, 8 warps (2 M x 4 N), warp tile 64x32.
// 3-stage cp.async ring, ONE __syncthreads per stage, uniform commits,
// TWO CTAs per SM (barrier bubbles of one CTA hidden by the other).
//   y[m,n] = sx_m * ( sum_g sw[n,g]*S1_g[m,n] ) - sx_m*zx_m*WSUM[n]
// ============================================================
__global__ void __launch_bounds__(THREADS, 2)
gemm_kernel(float* __restrict__ out) {
    extern __shared__ char smem[];
    const uint32_t swbase = smem_u32(smem);          // [32 g][128 n] fp32 = 16 KB
    const uint32_t tiles  = swbase + SW_BYTES;

    const int tid  = threadIdx.x;
    const int wid  = tid >> 5;
    const int lane = tid & 31;
    const int wm   = wid & 1;        // 0..1  (M)
    const int wn   = wid >> 1;       // 0..3  (N)

    const int m0 = blockIdx.y * TM;
    const int n0 = blockIdx.x * TN;

    // ---------- producer addressing ----------
    const int  r0  = tid >> 3;       // 0..31
    const int  c   = tid & 7;        // 16B chunk within 128B row
    const uint32_t swz = (uint32_t)(((c ^ (r0 & 7)) & 7) * 16);

    const signed char* gA = g_XQ + (size_t)(m0 + r0) * KDIM + c * 16;
    const signed char* gB = g_WQ + (size_t)(n0 + r0) * KDIM + c * 16;
    const uint32_t smA = tiles + (uint32_t)r0 * 128 + swz;
    const uint32_t smB = tiles + A_BYTES + (uint32_t)r0 * 128 + swz;

    // ---------- stage the group scales: sw_s[g][n] ----------
    for (int idx = tid; idx < KGROUPS * TN; idx += THREADS) {
        int n = idx >> 5;
        int g = idx & 31;
        ((float*)smem)[g * TN + n] = g_WS[(size_t)(n0 + n) * KGROUPS + g];
    }

    // ---------- consumer (ldmatrix) addressing ----------
    const uint32_t xr = (uint32_t)((lane & 7) * 16);
    // A x4 (m16 x k32): rows wm*64 + mf*16 + (lane&7) + ((lane>>3)&1)*8
    const uint32_t adA0 = tiles +
        (uint32_t)(wm * 64 + (lane & 7) + ((lane >> 3) & 1) * 8) * 128;
    const uint32_t ach = (uint32_t)((lane >> 4) * 16);
    // B x4 (2 n-frags x k32): rows wn*32 + g*16 + (lane&7) + (lane>>4)*8
    const uint32_t adB0 = tiles + A_BYTES +
        (uint32_t)(wn * 32 + (lane & 7) + (lane >> 4) * 8) * 128;
    const uint32_t bch = (uint32_t)(((lane >> 3) & 1) * 16);

    float facc[4][4][4];
#pragma unroll
    for (int i = 0; i < 4; i++)
#pragma unroll
        for (int j = 0; j < 4; j++)
#pragma unroll
            for (int q = 0; q < 4; q++) facc[i][j][q] = 0.0f;

    const int ncol2 = (lane & 3) * 2;

    // ---------- prologue: 2 stages in flight ----------
    LOAD_STAGE(0);
    LOAD_STAGE(1);

    // ---------- main loop: one quant group per iteration ----------
    for (int kb = 0; kb < NKB; kb++) {
        // Commits issued before this wait: 2 + kb (uniform, incl. tail).
        // wait<=1 pending => >= kb+1 complete => stage kb's commit done.
        CP_WAIT1();
        __syncthreads();
        // Single barrier per stage: writes below target stage (kb+2)%3,
        // overwriting stage (kb-1)%3, last read in iter kb-1; all warps have
        // passed THIS barrier, so those synchronous ldmatrix reads are done.

        const uint32_t so = (uint32_t)(kb % NSTAGES) * STAGE_BYTES;

        // group scales for this thread's 8 n-columns
        float swr[8];
        {
            const float* swp = (const float*)smem + (size_t)kb * TN + wn * 32 + ncol2;
#pragma unroll
            for (int nf = 0; nf < 4; nf++) {
                float2 s2 = *(const float2*)(swp + nf * 8);
                swr[2 * nf]     = s2.x;
                swr[2 * nf + 1] = s2.y;
            }
        }

        // B fragments for all 4 k-steps
        uint32_t bu[4][8];
#pragma unroll
        for (int ks = 0; ks < 4; ks++) {
            const uint32_t kc = (uint32_t)(ks * 32);
            LDSM_X4(bu[ks][0], bu[ks][1], bu[ks][2], bu[ks][3],
                    adB0 + so + ((kc + bch) ^ xr));
            LDSM_X4(bu[ks][4], bu[ks][5], bu[ks][6], bu[ks][7],
                    adB0 + 2048 + so + ((kc + bch) ^ xr));
        }

        // next stage's global loads; empty commit in tail keeps count uniform
        if (kb + 2 < NKB) { LOAD_STAGE(kb + 2); } else { CP_COMMIT(); }

#pragma unroll
        for (int mf = 0; mf < 4; mf++) {
            int ic[4][4];
#pragma unroll
            for (int nf = 0; nf < 4; nf++)
#pragma unroll
                for (int q = 0; q < 4; q++) ic[nf][q] = MAGIC_I;

#pragma unroll
            for (int ks = 0; ks < 4; ks++) {
                const uint32_t kc = (uint32_t)(ks * 32);
                uint32_t a[4];
                LDSM_X4(a[0], a[1], a[2], a[3],
                        adA0 + (uint32_t)mf * 2048 + so + ((kc + ach) ^ xr));
#pragma unroll
                for (int nf = 0; nf < 4; nf++)
                    MMAS8(ic[nf], a, bu[ks][2 * nf], bu[ks][2 * nf + 1]);
            }
            // fold group: S1 = float_bits(ic) - MAGIC (exact; |S1| < 2^22)
#pragma unroll
            for (int nf = 0; nf < 4; nf++) {
                facc[mf][nf][0] = __fmaf_rn(__fsub_rn(__int_as_float(ic[nf][0]), MAGIC_F),
                                            swr[2 * nf],     facc[mf][nf][0]);
                facc[mf][nf][1] = __fmaf_rn(__fsub_rn(__int_as_float(ic[nf][1]), MAGIC_F),
                                            swr[2 * nf + 1], facc[mf][nf][1]);
                facc[mf][nf][2] = __fmaf_rn(__fsub_rn(__int_as_float(ic[nf][2]), MAGIC_F),
                                            swr[2 * nf],     facc[mf][nf][2]);
                facc[mf][nf][3] = __fmaf_rn(__fsub_rn(__int_as_float(ic[nf][3]), MAGIC_F),
                                            swr[2 * nf + 1], facc[mf][nf][3]);
            }
        }
    }
    CP_WAIT0();

    // ---------- epilogue: y = sx*(facc - zx*WSUM[n]) ----------
#pragma unroll
    for (int mf = 0; mf < 4; mf++) {
        const int m_lo = m0 + wm * 64 + mf * 16 + (lane >> 2);
        const int m_hi = m_lo + 8;
        const float sx0 = g_SX[m_lo], zx0 = g_ZX[m_lo];
        const float sx1 = g_SX[m_hi], zx1 = g_ZX[m_hi];
        float* row_lo = out + (size_t)m_lo * NDIM + n0 + wn * 32 + ncol2;
        float* row_hi = out + (size_t)m_hi * NDIM + n0 + wn * 32 + ncol2;
#pragma unroll
        for (int nf = 0; nf < 4; nf++) {
            const int ng = n0 + wn * 32 + nf * 8 + ncol2;
            const float ws0 = g_WSUM[ng];
            const float ws1 = g_WSUM[ng + 1];
            float2 v0, v1;
            v0.x = sx0 * (facc[mf][nf][0] - zx0 * ws0);
            v0.y = sx0 * (facc[mf][nf][1] - zx0 * ws1);
            v1.x = sx1 * (facc[mf][nf][2] - zx1 * ws0);
            v1.y = sx1 * (facc[mf][nf][3] - zx1 * ws1);
            *(float2*)(row_lo + nf * 8) = v0;
            *(float2*)(row_hi + nf * 8) = v1;
        }
    }
}

// ============================================================
// Launcher
// ============================================================
extern "C" void kernel_launch(void* const* d_in, const int* in_sizes, int n_in,
                              void* d_out, int out_size) {
    const float* x = (const float*)d_in[0];   // [4, 2048, 4096] fp32
    const float* w = (const float*)d_in[1];   // [4096, 4096] fp32
    float* out = (float*)d_out;               // [4, 2048, 4096] fp32

    cudaFuncSetAttribute(gemm_kernel, cudaFuncAttributeMaxDynamicSharedMemorySize, GEMM_SMEM);

    w_quant_kernel<<<16384, 256>>>(w);        // 131072 groups / 8 per block
    wsum_kernel<<<512, 256>>>();              // 4096 rows / 8 per block
    act_quant_kernel<<<MROWS, 256>>>(x);
    gemm_kernel<<<dim3(NDIM / TN, MROWS / TM), THREADS, GEMM_SMEM>>>(out);
}

// round 11
// speedup vs baseline: 1.1326x; 1.1326x over previous
#include <cuda_runtime.h>
#include <cstdint>
#include <cstddef>

// ============================================================
// Problem dims (fixed)
// ============================================================
#define MROWS 8192
#define NDIM  4096
#define KDIM  4096
#define KGROUPS 32                   // 4096 / 128 quant groups per row

// GEMM tiling: CTA 128x256, 8 warps (2 M x 4 N), warp tile 64x64
#define TM 128
#define TN 256
#define KB 128                       // K int8 per stage = ONE quant group
#define NKB (KDIM / KB)              // 32
#define NSTAGES 4
#define A_BYTES (TM * 128)           // 16384
#define B_BYTES (TN * 128)           // 32768
#define STAGE_BYTES (A_BYTES + B_BYTES)            // 49152
#define SW_BYTES (KGROUPS * TN * 4)                // 32768 group scales in SMEM
#define GEMM_SMEM (SW_BYTES + NSTAGES * STAGE_BYTES)   // 229376 (<= 232448 max)

#define THREADS 256                  // 8 warps

// int bit pattern of 12582912.0f (2^23 + 2^22): magic bias for exact int->float
#define MAGIC_I 0x4B400000
#define MAGIC_F 12582912.0f

// ============================================================
// Scratch (static __device__ — no runtime allocation)
// ============================================================
__device__ signed char g_XQ[(size_t)MROWS * KDIM];   // 32 MB: qx int8 (exact)
__device__ signed char g_WQ[(size_t)NDIM * KDIM];    // 16 MB: wq = (q - z) in [0,15]
__device__ float g_SX[MROWS];                        // activation scale per row
__device__ float g_ZX[MROWS];                        // activation zero per row
__device__ float g_WS[(size_t)NDIM * KGROUPS];       // weight group scale sw[n][g]
__device__ float g_WGS[(size_t)NDIM * KGROUPS];      // sw[n][g] * sum_{k in g} wq
__device__ float g_WSUM[NDIM];                       // sum_k w_deq[n][k]

// ============================================================
// PTX helpers (sm_100 baseline ISA — no 'a'-suffix features)
// ============================================================
__device__ __forceinline__ uint32_t smem_u32(const void* p) {
    uint32_t a;
    asm("{ .reg .u64 t; cvta.to.shared.u64 t, %1; cvt.u32.u64 %0, t; }" : "=r"(a) : "l"(p));
    return a;
}

#define CP16(smem_addr, gptr) \
    asm volatile("cp.async.cg.shared.global [%0], [%1], 16;" :: "r"(smem_addr), "l"(gptr) : "memory")
#define CP_COMMIT()  asm volatile("cp.async.commit_group;" ::: "memory")
#define CP_WAIT2()   asm volatile("cp.async.wait_group 2;" ::: "memory")
#define CP_WAIT0()   asm volatile("cp.async.wait_group 0;" ::: "memory")

#define LDSM_X4(r0, r1, r2, r3, addr)                                        \
    asm volatile("ldmatrix.sync.aligned.m8n8.x4.shared.b16 {%0,%1,%2,%3}, [%4];" \
                 : "=r"(r0), "=r"(r1), "=r"(r2), "=r"(r3) : "r"(addr))

#define MMAS8(c, a, b0, b1)                                                  \
    asm volatile("mma.sync.aligned.m16n8k32.row.col.s32.s8.s8.s32 "          \
                 "{%0,%1,%2,%3}, {%4,%5,%6,%7}, {%8,%9}, {%0,%1,%2,%3};"     \
                 : "+r"((c)[0]), "+r"((c)[1]), "+r"((c)[2]), "+r"((c)[3])    \
                 : "r"((a)[0]), "r"((a)[1]), "r"((a)[2]), "r"((a)[3]),       \
                   "r"((b0)), "r"((b1)))

// Stage load: A rows {r0,+32,+64,+96}; B rows {r0,+32,...,+224}.
// 256 threads x 12 cp.async = 3072 x 16B = 48 KB per stage.
#define LOAD_STAGE(kb)                                                        \
    do {                                                                      \
        const uint32_t so_ = (uint32_t)((kb) & (NSTAGES - 1)) * STAGE_BYTES;  \
        const signed char* pA = gA + (size_t)(kb) * 128;                      \
        const signed char* pB = gB + (size_t)(kb) * 128;                      \
        CP16(smA + so_,             pA);                                      \
        CP16(smA + so_ + 32 * 128,  pA + (size_t)32 * KDIM);                  \
        CP16(smA + so_ + 64 * 128,  pA + (size_t)64 * KDIM);                  \
        CP16(smA + so_ + 96 * 128,  pA + (size_t)96 * KDIM);                  \
        CP16(smB + so_,             pB);                                      \
        CP16(smB + so_ + 32 * 128,  pB + (size_t)32 * KDIM);                  \
        CP16(smB + so_ + 64 * 128,  pB + (size_t)64 * KDIM);                  \
        CP16(smB + so_ + 96 * 128,  pB + (size_t)96 * KDIM);                  \
        CP16(smB + so_ + 128 * 128, pB + (size_t)128 * KDIM);                 \
        CP16(smB + so_ + 160 * 128, pB + (size_t)160 * KDIM);                 \
        CP16(smB + so_ + 192 * 128, pB + (size_t)192 * KDIM);                 \
        CP16(smB + so_ + 224 * 128, pB + (size_t)224 * KDIM);                 \
        CP_COMMIT();                                                          \
    } while (0)

// ============================================================
// Kernel 1: weight group quant (gs=128, nbit=4, asym) -> int8 wq + scales
// ============================================================
__global__ void __launch_bounds__(256) w_quant_kernel(const float* __restrict__ w) {
    int g    = blockIdx.x * 8 + (threadIdx.x >> 5);   // group id = n*32 + gk
    int lane = threadIdx.x & 31;
    const float4 f = ((const float4*)(w + (size_t)g * 128))[lane];

    float v[4] = {f.x, f.y, f.z, f.w};
    float mn = fminf(fminf(v[0], v[1]), fminf(v[2], v[3]));
    float mx = fmaxf(fmaxf(v[0], v[1]), fmaxf(v[2], v[3]));
#pragma unroll
    for (int off = 16; off > 0; off >>= 1) {
        mn = fminf(mn, __shfl_xor_sync(0xffffffffu, mn, off));
        mx = fmaxf(mx, __shfl_xor_sync(0xffffffffu, mx, off));
    }
    float sc = __fdiv_rn(mx - mn, 15.0f);
    if (!(sc > 0.0f)) sc = 1.0f;
    float z = -8.0f - rintf(__fdiv_rn(mn, sc));

    float gsum = 0.0f;
    signed char o[4];
#pragma unroll
    for (int j = 0; j < 4; j++) {
        float q = rintf(__fdiv_rn(v[j], sc)) + z;
        q = fminf(fmaxf(q, -8.0f), 7.0f);
        float wq = q - z;                 // exact small integer in [0,15]
        gsum += wq;
        o[j] = (signed char)__float2int_rn(wq);
    }
    ((char4*)(g_WQ + (size_t)g * 128))[lane] = make_char4(o[0], o[1], o[2], o[3]);
#pragma unroll
    for (int off = 16; off > 0; off >>= 1)
        gsum += __shfl_xor_sync(0xffffffffu, gsum, off);
    if (lane == 0) {
        g_WS[g]  = sc;
        g_WGS[g] = sc * gsum;
    }
}

// ============================================================
// Kernel 1b: WSUM[n] = sum_g g_WGS[n*32+g]
// ============================================================
__global__ void __launch_bounds__(256) wsum_kernel() {
    int n    = blockIdx.x * 8 + (threadIdx.x >> 5);
    int lane = threadIdx.x & 31;
    float v = g_WGS[(size_t)n * KGROUPS + lane];
#pragma unroll
    for (int off = 16; off > 0; off >>= 1)
        v += __shfl_xor_sync(0xffffffffu, v, off);
    if (lane == 0) g_WSUM[n] = v;
}

// ============================================================
// Kernel 2: activation dynamic per-row int8 quant -> qx int8, sx, zx
// ============================================================
__global__ void __launch_bounds__(256) act_quant_kernel(const float* __restrict__ x) {
    int row = blockIdx.x;
    int tid = threadIdx.x;
    const float4* xr4 = (const float4*)(x + (size_t)row * KDIM);

    float vals[16];
    float mn = 3.4e38f, mx = -3.4e38f;
#pragma unroll
    for (int j = 0; j < 4; j++) {
        float4 f = xr4[tid + j * 256];
        vals[4 * j + 0] = f.x; vals[4 * j + 1] = f.y;
        vals[4 * j + 2] = f.z; vals[4 * j + 3] = f.w;
        mn = fminf(mn, fminf(fminf(f.x, f.y), fminf(f.z, f.w)));
        mx = fmaxf(mx, fmaxf(fmaxf(f.x, f.y), fmaxf(f.z, f.w)));
    }
#pragma unroll
    for (int off = 16; off > 0; off >>= 1) {
        mn = fminf(mn, __shfl_xor_sync(0xffffffffu, mn, off));
        mx = fmaxf(mx, __shfl_xor_sync(0xffffffffu, mx, off));
    }
    __shared__ float smin[8], smax[8];
    __shared__ float s_sc, s_z;
    if ((tid & 31) == 0) { smin[tid >> 5] = mn; smax[tid >> 5] = mx; }
    __syncthreads();
    if (tid == 0) {
        float rmn = smin[0], rmx = smax[0];
#pragma unroll
        for (int i = 1; i < 8; i++) { rmn = fminf(rmn, smin[i]); rmx = fmaxf(rmx, smax[i]); }
        float sc = __fdiv_rn(rmx - rmn, 255.0f);
        if (!(sc > 0.0f)) sc = 1.0f;
        float z = -128.0f - rintf(__fdiv_rn(rmn, sc));
        s_sc = sc; s_z = z;
        g_SX[row] = sc;
        g_ZX[row] = z;
    }
    __syncthreads();
    float sc = s_sc, z = s_z;
    char4* outp4 = (char4*)(g_XQ + (size_t)row * KDIM);
#pragma unroll
    for (int j = 0; j < 4; j++) {
        signed char o[4];
#pragma unroll
        for (int e = 0; e < 4; e++) {
            float q = rintf(__fdiv_rn(vals[4 * j + e], sc)) + z;
            q = fminf(fmaxf(q, -128.0f), 127.0f);
            o[e] = (signed char)__float2int_rn(q);
        }
        outp4[tid + j * 256] = make_char4(o[0], o[1], o[2], o[3]);
    }
}

// ============================================================
// Kernel 3: int8 IMMA GEMM (magic-bias group fold, exact)
// CTA 128x256, 8 warps (2 M x 4 N), warp tile 64x64 -> 128 B smem per MMA.
// 4-stage cp.async ring, one __syncthreads per stage, uniform commits.
// Group scales read from SMEM at fold time (saves 16 regs).
//   y[m,n] = sx_m * ( sum_g sw[n,g]*S1_g[m,n] ) - sx_m*zx_m*WSUM[n]
// ============================================================
__global__ void __launch_bounds__(THREADS, 1)
gemm_kernel(float* __restrict__ out) {
    extern __shared__ char smem[];
    const uint32_t tiles = smem_u32(smem) + SW_BYTES;

    const int tid  = threadIdx.x;
    const int wid  = tid >> 5;
    const int lane = tid & 31;
    const int wm   = wid & 1;        // 0..1  (M)
    const int wn   = wid >> 1;       // 0..3  (N)

    const int m0 = blockIdx.y * TM;
    const int n0 = blockIdx.x * TN;

    // ---------- producer addressing ----------
    const int  r0  = tid >> 3;       // 0..31
    const int  c   = tid & 7;        // 16B chunk within 128B row
    const uint32_t swz = (uint32_t)(((c ^ (r0 & 7)) & 7) * 16);

    const signed char* gA = g_XQ + (size_t)(m0 + r0) * KDIM + c * 16;
    const signed char* gB = g_WQ + (size_t)(n0 + r0) * KDIM + c * 16;
    const uint32_t smA = tiles + (uint32_t)r0 * 128 + swz;
    const uint32_t smB = tiles + A_BYTES + (uint32_t)r0 * 128 + swz;

    // ---------- stage the group scales: sw_s[g][n] (g-major rows of 256) ----------
    for (int idx = tid; idx < KGROUPS * TN; idx += THREADS) {
        int n = idx >> 5;            // 0..255 (g contiguous in gmem -> coalesced)
        int g = idx & 31;
        ((float*)smem)[g * TN + n] = g_WS[(size_t)(n0 + n) * KGROUPS + g];
    }

    // ---------- consumer (ldmatrix) addressing ----------
    const uint32_t xr = (uint32_t)((lane & 7) * 16);
    // A x4 (m16 x k32): rows wm*64 + mf*16 + (lane&7) + ((lane>>3)&1)*8
    const uint32_t adA0 = tiles +
        (uint32_t)(wm * 64 + (lane & 7) + ((lane >> 3) & 1) * 8) * 128;
    const uint32_t ach = (uint32_t)((lane >> 4) * 16);
    // B x4 (2 n-frags per g, g=0..3): rows wn*64 + g*16 + (lane&7) + (lane>>4)*8
    const uint32_t adB0 = tiles + A_BYTES +
        (uint32_t)(wn * 64 + (lane & 7) + (lane >> 4) * 8) * 128;
    const uint32_t bch = (uint32_t)(((lane >> 3) & 1) * 16);

    float facc[4][8][4];
#pragma unroll
    for (int i = 0; i < 4; i++)
#pragma unroll
        for (int j = 0; j < 8; j++)
#pragma unroll
            for (int q = 0; q < 4; q++) facc[i][j][q] = 0.0f;

    const int ncol2 = (lane & 3) * 2;

    // ---------- prologue: 3 stages in flight ----------
    LOAD_STAGE(0);
    LOAD_STAGE(1);
    LOAD_STAGE(2);

    // ---------- main loop: one quant group per iteration ----------
    for (int kb = 0; kb < NKB; kb++) {
        // Commits before this wait: 3 + kb (uniform incl. tail).
        // wait<=2 pending => stage kb's commit complete.
        CP_WAIT2();
        __syncthreads();
        // Single barrier per stage: new writes target stage (kb+3)%4 which was
        // last read in iter kb-1; all warps passed THIS barrier => reads done.

        const uint32_t so = (uint32_t)(kb & (NSTAGES - 1)) * STAGE_BYTES;

        // B fragments for all 4 k-steps: 8 n-frags (4 x4-ldsm) each
        uint32_t bu[4][16];
#pragma unroll
        for (int ks = 0; ks < 4; ks++) {
            const uint32_t kc = (uint32_t)(ks * 32);
            const uint32_t ab = adB0 + so + ((kc + bch) ^ xr);
#pragma unroll
            for (int g = 0; g < 4; g++)
                LDSM_X4(bu[ks][4 * g], bu[ks][4 * g + 1],
                        bu[ks][4 * g + 2], bu[ks][4 * g + 3],
                        ab + (uint32_t)g * 2048);
        }

        // next stage's global loads; empty commit in tail keeps count uniform
        if (kb + 3 < NKB) { LOAD_STAGE(kb + 3); } else { CP_COMMIT(); }

        const float* swp = (const float*)smem + (size_t)kb * TN + wn * 64 + ncol2;

#pragma unroll
        for (int mf = 0; mf < 4; mf++) {
            int ic[8][4];
#pragma unroll
            for (int nf = 0; nf < 8; nf++)
#pragma unroll
                for (int q = 0; q < 4; q++) ic[nf][q] = MAGIC_I;

#pragma unroll
            for (int ks = 0; ks < 4; ks++) {
                const uint32_t kc = (uint32_t)(ks * 32);
                uint32_t a[4];
                LDSM_X4(a[0], a[1], a[2], a[3],
                        adA0 + (uint32_t)mf * 2048 + so + ((kc + ach) ^ xr));
#pragma unroll
                for (int nf = 0; nf < 8; nf++)
                    MMAS8(ic[nf], a, bu[ks][2 * nf], bu[ks][2 * nf + 1]);
            }
            // fold group: S1 = float_bits(ic) - MAGIC (exact; |S1| < 2^22).
            // Group scales read from SMEM as float2 transients (reg relief).
#pragma unroll
            for (int nf = 0; nf < 8; nf++) {
                float2 s2 = *(const float2*)(swp + nf * 8);
                facc[mf][nf][0] = __fmaf_rn(__fsub_rn(__int_as_float(ic[nf][0]), MAGIC_F),
                                            s2.x, facc[mf][nf][0]);
                facc[mf][nf][1] = __fmaf_rn(__fsub_rn(__int_as_float(ic[nf][1]), MAGIC_F),
                                            s2.y, facc[mf][nf][1]);
                facc[mf][nf][2] = __fmaf_rn(__fsub_rn(__int_as_float(ic[nf][2]), MAGIC_F),
                                            s2.x, facc[mf][nf][2]);
                facc[mf][nf][3] = __fmaf_rn(__fsub_rn(__int_as_float(ic[nf][3]), MAGIC_F),
                                            s2.y, facc[mf][nf][3]);
            }
        }
    }
    CP_WAIT0();

    // ---------- epilogue: y = sx*(facc - zx*WSUM[n]) ----------
#pragma unroll
    for (int mf = 0; mf < 4; mf++) {
        const int m_lo = m0 + wm * 64 + mf * 16 + (lane >> 2);
        const int m_hi = m_lo + 8;
        const float sx0 = g_SX[m_lo], zx0 = g_ZX[m_lo];
        const float sx1 = g_SX[m_hi], zx1 = g_ZX[m_hi];
        float* row_lo = out + (size_t)m_lo * NDIM + n0 + wn * 64 + ncol2;
        float* row_hi = out + (size_t)m_hi * NDIM + n0 + wn * 64 + ncol2;
#pragma unroll
        for (int nf = 0; nf < 8; nf++) {
            const int ng = n0 + wn * 64 + nf * 8 + ncol2;
            const float ws0 = g_WSUM[ng];
            const float ws1 = g_WSUM[ng + 1];
            float2 v0, v1;
            v0.x = sx0 * (facc[mf][nf][0] - zx0 * ws0);
            v0.y = sx0 * (facc[mf][nf][1] - zx0 * ws1);
            v1.x = sx1 * (facc[mf][nf][2] - zx1 * ws0);
            v1.y = sx1 * (facc[mf][nf][3] - zx1 * ws1);
            *(float2*)(row_lo + nf * 8) = v0;
            *(float2*)(row_hi + nf * 8) = v1;
        }
    }
}

// ============================================================
// Launcher
// ============================================================
extern "C" void kernel_launch(void* const* d_in, const int* in_sizes, int n_in,
                              void* d_out, int out_size) {
    const float* x = (const float*)d_in[0];   // [4, 2048, 4096] fp32
    const float* w = (const float*)d_in[1];   // [4096, 4096] fp32
    float* out = (float*)d_out;               // [4, 2048, 4096] fp32

    cudaFuncSetAttribute(gemm_kernel, cudaFuncAttributeMaxDynamicSharedMemorySize, GEMM_SMEM);

    w_quant_kernel<<<16384, 256>>>(w);        // 131072 groups / 8 per block
    wsum_kernel<<<512, 256>>>();              // 4096 rows / 8 per block
    act_quant_kernel<<<MROWS, 256>>>(x);
    gemm_kernel<<<dim3(NDIM / TN, MROWS / TM), THREADS, GEMM_SMEM>>>(out);
}

// round 12
// speedup vs baseline: 1.1542x; 1.0190x over previous
#include <cuda_runtime.h>
#include <cstdint>
#include <cstddef>

// ============================================================
// Problem dims (fixed)
// ============================================================
#define MROWS 8192
#define NDIM  4096
#define KDIM  4096
#define KGROUPS 32                   // 4096 / 128 quant groups per row

// GEMM tiling: CTA 128x128, 8 warps (2 M x 4 N), warp tile 64x32  (R5 config)
#define TM 128
#define TN 128
#define KB 128                       // K int8 per stage = ONE quant group
#define NKB (KDIM / KB)              // 32
#define NSTAGES 4
#define A_BYTES (TM * 128)           // 16384
#define B_BYTES (TN * 128)           // 16384
#define STAGE_BYTES (A_BYTES + B_BYTES)            // 32768
#define SW_BYTES (KGROUPS * TN * 4)                // 16384 group scales in SMEM
#define GEMM_SMEM (SW_BYTES + NSTAGES * STAGE_BYTES)   // 147456

#define THREADS 256                  // 8 warps — measured-best config (R5)

// ============================================================
// Scratch (static __device__ — no runtime allocation)
// ============================================================
__device__ signed char g_XQ[(size_t)MROWS * KDIM];   // 32 MB: qx int8 (exact)
__device__ signed char g_WQ[(size_t)NDIM * KDIM];    // 16 MB: wq = (q - z) in [0,15]
__device__ float g_SX[MROWS];                        // activation scale per row
__device__ float g_ZX[MROWS];                        // activation zero per row
__device__ float g_WS[(size_t)NDIM * KGROUPS];       // weight group scale sw[n][g]
__device__ float g_WGS[(size_t)NDIM * KGROUPS];      // sw[n][g] * sum_{k in g} wq
__device__ float g_WSUM[NDIM];                       // sum_k w_deq[n][k]

// ============================================================
// PTX helpers (sm_100 baseline ISA — no 'a'-suffix features)
// ============================================================
__device__ __forceinline__ uint32_t smem_u32(const void* p) {
    uint32_t a;
    asm("{ .reg .u64 t; cvta.to.shared.u64 t, %1; cvt.u32.u64 %0, t; }" : "=r"(a) : "l"(p));
    return a;
}

#define CP16(smem_addr, gptr) \
    asm volatile("cp.async.cg.shared.global [%0], [%1], 16;" :: "r"(smem_addr), "l"(gptr) : "memory")
#define CP_COMMIT()  asm volatile("cp.async.commit_group;" ::: "memory")
#define CP_WAIT2()   asm volatile("cp.async.wait_group 2;" ::: "memory")
#define CP_WAIT0()   asm volatile("cp.async.wait_group 0;" ::: "memory")

#define LDSM_X4(r0, r1, r2, r3, addr)                                        \
    asm volatile("ldmatrix.sync.aligned.m8n8.x4.shared.b16 {%0,%1,%2,%3}, [%4];" \
                 : "=r"(r0), "=r"(r1), "=r"(r2), "=r"(r3) : "r"(addr))

#define MMAS8(c, a, b0, b1)                                                  \
    asm volatile("mma.sync.aligned.m16n8k32.row.col.s32.s8.s8.s32 "          \
                 "{%0,%1,%2,%3}, {%4,%5,%6,%7}, {%8,%9}, {%0,%1,%2,%3};"     \
                 : "+r"((c)[0]), "+r"((c)[1]), "+r"((c)[2]), "+r"((c)[3])    \
                 : "r"((a)[0]), "r"((a)[1]), "r"((a)[2]), "r"((a)[3]),       \
                   "r"((b0)), "r"((b1)))

// Stage load: A rows {r0,+32,+64,+96}, B rows same; one 16B chunk/row/thread.
#define LOAD_STAGE(kb)                                                        \
    do {                                                                      \
        const uint32_t so_ = (uint32_t)((kb) & (NSTAGES - 1)) * STAGE_BYTES;  \
        const signed char* pA = gA + (size_t)(kb) * 128;                      \
        const signed char* pB = gB + (size_t)(kb) * 128;                      \
        CP16(smA + so_,            pA);                                       \
        CP16(smA + so_ + 32 * 128, pA + (size_t)32 * KDIM);                   \
        CP16(smA + so_ + 64 * 128, pA + (size_t)64 * KDIM);                   \
        CP16(smA + so_ + 96 * 128, pA + (size_t)96 * KDIM);                   \
        CP16(smB + so_,            pB);                                       \
        CP16(smB + so_ + 32 * 128, pB + (size_t)32 * KDIM);                   \
        CP16(smB + so_ + 64 * 128, pB + (size_t)64 * KDIM);                   \
        CP16(smB + so_ + 96 * 128, pB + (size_t)96 * KDIM);                   \
        CP_COMMIT();                                                          \
    } while (0)

// ============================================================
// Kernel 1: weight group quant (gs=128, nbit=4, asym) -> int8 wq + scales
// 4 groups per warp -> MLP=4 on the LDG.128s (hides DRAM latency).
// ============================================================
__global__ void __launch_bounds__(256) w_quant_kernel(const float* __restrict__ w) {
    int gbase = blockIdx.x * 32 + (threadIdx.x >> 5) * 4;   // 4 groups per warp
    int lane  = threadIdx.x & 31;

    float4 f[4];
#pragma unroll
    for (int i = 0; i < 4; i++)
        f[i] = ((const float4*)(w + (size_t)(gbase + i) * 128))[lane];

#pragma unroll
    for (int i = 0; i < 4; i++) {
        int g = gbase + i;
        float v[4] = {f[i].x, f[i].y, f[i].z, f[i].w};
        float mn = fminf(fminf(v[0], v[1]), fminf(v[2], v[3]));
        float mx = fmaxf(fmaxf(v[0], v[1]), fmaxf(v[2], v[3]));
#pragma unroll
        for (int off = 16; off > 0; off >>= 1) {
            mn = fminf(mn, __shfl_xor_sync(0xffffffffu, mn, off));
            mx = fmaxf(mx, __shfl_xor_sync(0xffffffffu, mx, off));
        }
        float sc = __fdiv_rn(mx - mn, 15.0f);
        if (!(sc > 0.0f)) sc = 1.0f;
        float z = -8.0f - rintf(__fdiv_rn(mn, sc));

        float gsum = 0.0f;
        signed char o[4];
#pragma unroll
        for (int j = 0; j < 4; j++) {
            float q = rintf(__fdiv_rn(v[j], sc)) + z;
            q = fminf(fmaxf(q, -8.0f), 7.0f);
            float wq = q - z;             // exact small integer in [0,15]
            gsum += wq;
            o[j] = (signed char)__float2int_rn(wq);
        }
        ((char4*)(g_WQ + (size_t)g * 128))[lane] = make_char4(o[0], o[1], o[2], o[3]);
#pragma unroll
        for (int off = 16; off > 0; off >>= 1)
            gsum += __shfl_xor_sync(0xffffffffu, gsum, off);
        if (lane == 0) {
            g_WS[g]  = sc;
            g_WGS[g] = sc * gsum;
        }
    }
}

// ============================================================
// Kernel 1b: WSUM[n] = sum_g g_WGS[n*32+g]
// ============================================================
__global__ void __launch_bounds__(256) wsum_kernel() {
    int n    = blockIdx.x * 8 + (threadIdx.x >> 5);
    int lane = threadIdx.x & 31;
    float v = g_WGS[(size_t)n * KGROUPS + lane];
#pragma unroll
    for (int off = 16; off > 0; off >>= 1)
        v += __shfl_xor_sync(0xffffffffu, v, off);
    if (lane == 0) g_WSUM[n] = v;
}

// ============================================================
// Kernel 2: activation dynamic per-row int8 quant -> qx int8, sx, zx
// ============================================================
__global__ void __launch_bounds__(256) act_quant_kernel(const float* __restrict__ x) {
    int row = blockIdx.x;
    int tid = threadIdx.x;
    const float4* xr4 = (const float4*)(x + (size_t)row * KDIM);

    float vals[16];
    float mn = 3.4e38f, mx = -3.4e38f;
#pragma unroll
    for (int j = 0; j < 4; j++) {
        float4 f = xr4[tid + j * 256];
        vals[4 * j + 0] = f.x; vals[4 * j + 1] = f.y;
        vals[4 * j + 2] = f.z; vals[4 * j + 3] = f.w;
        mn = fminf(mn, fminf(fminf(f.x, f.y), fminf(f.z, f.w)));
        mx = fmaxf(mx, fmaxf(fmaxf(f.x, f.y), fmaxf(f.z, f.w)));
    }
#pragma unroll
    for (int off = 16; off > 0; off >>= 1) {
        mn = fminf(mn, __shfl_xor_sync(0xffffffffu, mn, off));
        mx = fmaxf(mx, __shfl_xor_sync(0xffffffffu, mx, off));
    }
    __shared__ float smin[8], smax[8];
    __shared__ float s_sc, s_z;
    if ((tid & 31) == 0) { smin[tid >> 5] = mn; smax[tid >> 5] = mx; }
    __syncthreads();
    if (tid == 0) {
        float rmn = smin[0], rmx = smax[0];
#pragma unroll
        for (int i = 1; i < 8; i++) { rmn = fminf(rmn, smin[i]); rmx = fmaxf(rmx, smax[i]); }
        float sc = __fdiv_rn(rmx - rmn, 255.0f);
        if (!(sc > 0.0f)) sc = 1.0f;
        float z = -128.0f - rintf(__fdiv_rn(rmn, sc));
        s_sc = sc; s_z = z;
        g_SX[row] = sc;
        g_ZX[row] = z;
    }
    __syncthreads();
    float sc = s_sc, z = s_z;
    char4* outp4 = (char4*)(g_XQ + (size_t)row * KDIM);
#pragma unroll
    for (int j = 0; j < 4; j++) {
        signed char o[4];
#pragma unroll
        for (int e = 0; e < 4; e++) {
            float q = rintf(__fdiv_rn(vals[4 * j + e], sc)) + z;
            q = fminf(fmaxf(q, -128.0f), 127.0f);
            o[e] = (signed char)__float2int_rn(q);
        }
        outp4[tid + j * 256] = make_char4(o[0], o[1], o[2], o[3]);
    }
}

// ============================================================
// Kernel 3: int8 IMMA GEMM — R5 configuration (measured best 529.7 us)
// CTA 128x128, 8 warps (2 M x 4 N), warp tile 64x32; K-stage = 1 group.
// 4-stage cp.async ring; uniform tail commits fix R5's latent tail race.
//   y[m,n] = sx_m * ( sum_g sw[n,g]*S1_g[m,n] ) - sx_m*zx_m*WSUM[n]
//   S1_g exact int32 (|.| < 2^22 -> exact I2F).
// ============================================================
__global__ void __launch_bounds__(THREADS, 1)
gemm_kernel(float* __restrict__ out) {
    extern __shared__ char smem[];
    const uint32_t swbase = smem_u32(smem);          // [32 g][128 n] fp32 = 16 KB
    const uint32_t tiles  = swbase + SW_BYTES;

    const int tid  = threadIdx.x;
    const int wid  = tid >> 5;
    const int lane = tid & 31;
    const int wm   = wid & 1;        // 0..1  (M)
    const int wn   = wid >> 1;       // 0..3  (N)

    const int m0 = blockIdx.y * TM;
    const int n0 = blockIdx.x * TN;

    // ---------- producer addressing ----------
    const int  r0  = tid >> 3;       // 0..31
    const int  c   = tid & 7;        // 16B chunk within 128B row
    const uint32_t swz = (uint32_t)(((c ^ (r0 & 7)) & 7) * 16);

    const signed char* gA = g_XQ + (size_t)(m0 + r0) * KDIM + c * 16;
    const signed char* gB = g_WQ + (size_t)(n0 + r0) * KDIM + c * 16;
    const uint32_t smA = tiles + (uint32_t)r0 * 128 + swz;
    const uint32_t smB = tiles + A_BYTES + (uint32_t)r0 * 128 + swz;

    // ---------- prologue: 3 stages in flight (issued FIRST so the scale
    // staging LDGs below overlap with cp.async flight time) ----------
    LOAD_STAGE(0);
    LOAD_STAGE(1);
    LOAD_STAGE(2);

    // ---------- stage the group scales: sw_s[g][n] = g_WS[(n0+n)*32 + g] ----------
    for (int idx = tid; idx < KGROUPS * TN; idx += THREADS) {
        int n = idx >> 5;            // g contiguous in gmem -> coalesced LDG
        int g = idx & 31;
        ((float*)smem)[g * TN + n] = g_WS[(size_t)(n0 + n) * KGROUPS + g];
    }

    // ---------- consumer (ldmatrix) addressing ----------
    const uint32_t xr = (uint32_t)((lane & 7) * 16);
    // A x4 (m16 x k32): rows wm*64 + mf*16 + (lane&7) + ((lane>>3)&1)*8
    const uint32_t adA0 = tiles +
        (uint32_t)(wm * 64 + (lane & 7) + ((lane >> 3) & 1) * 8) * 128;
    const uint32_t ach = (uint32_t)((lane >> 4) * 16);
    // B x4 (2 n-frags x k32): rows wn*32 + g*16 + (lane&7) + (lane>>4)*8
    const uint32_t adB0 = tiles + A_BYTES +
        (uint32_t)(wn * 32 + (lane & 7) + (lane >> 4) * 8) * 128;
    const uint32_t bch = (uint32_t)(((lane >> 3) & 1) * 16);

    float facc[4][4][4];
#pragma unroll
    for (int i = 0; i < 4; i++)
#pragma unroll
        for (int j = 0; j < 4; j++)
#pragma unroll
            for (int q = 0; q < 4; q++) facc[i][j][q] = 0.0f;

    const int ncol2 = (lane & 3) * 2;

    // ---------- main loop: one quant group per iteration ----------
    for (int kb = 0; kb < NKB; kb++) {
        // Commits issued before this wait: 3 + kb (uniform, incl. tail).
        // wait<=2 pending => >= kb+1 complete => stage kb's commit done.
        CP_WAIT2();
        __syncthreads();

        // next stage's global loads; empty commit in tail keeps count uniform
        if (kb + 3 < NKB) { LOAD_STAGE(kb + 3); } else { CP_COMMIT(); }

        const uint32_t so = (uint32_t)(kb & (NSTAGES - 1)) * STAGE_BYTES;

        // group scales for this thread's 8 n-columns
        float swr[8];
        {
            const float* swp = (const float*)smem + (size_t)kb * TN + wn * 32 + ncol2;
#pragma unroll
            for (int nf = 0; nf < 4; nf++) {
                float2 s2 = *(const float2*)(swp + nf * 8);
                swr[2 * nf]     = s2.x;
                swr[2 * nf + 1] = s2.y;
            }
        }

        // B fragments for all 4 k-steps
        uint32_t bu[4][8];
#pragma unroll
        for (int ks = 0; ks < 4; ks++) {
            const uint32_t kc = (uint32_t)(ks * 32);
            LDSM_X4(bu[ks][0], bu[ks][1], bu[ks][2], bu[ks][3],
                    adB0 + so + ((kc + bch) ^ xr));
            LDSM_X4(bu[ks][4], bu[ks][5], bu[ks][6], bu[ks][7],
                    adB0 + 2048 + so + ((kc + bch) ^ xr));
        }

#pragma unroll
        for (int mf = 0; mf < 4; mf++) {
            int ic[4][4];
#pragma unroll
            for (int nf = 0; nf < 4; nf++)
#pragma unroll
                for (int q = 0; q < 4; q++) ic[nf][q] = 0;

#pragma unroll
            for (int ks = 0; ks < 4; ks++) {
                const uint32_t kc = (uint32_t)(ks * 32);
                uint32_t a[4];
                LDSM_X4(a[0], a[1], a[2], a[3],
                        adA0 + (uint32_t)mf * 2048 + so + ((kc + ach) ^ xr));
#pragma unroll
                for (int nf = 0; nf < 4; nf++)
                    MMAS8(ic[nf], a, bu[ks][2 * nf], bu[ks][2 * nf + 1]);
            }
            // fold group: facc += sw * S1  (I2F exact: |S1| < 2^22)
#pragma unroll
            for (int nf = 0; nf < 4; nf++) {
                facc[mf][nf][0] += __int2float_rn(ic[nf][0]) * swr[2 * nf];
                facc[mf][nf][1] += __int2float_rn(ic[nf][1]) * swr[2 * nf + 1];
                facc[mf][nf][2] += __int2float_rn(ic[nf][2]) * swr[2 * nf];
                facc[mf][nf][3] += __int2float_rn(ic[nf][3]) * swr[2 * nf + 1];
            }
        }
        __syncthreads();
    }
    CP_WAIT0();

    // ---------- epilogue: y = sx*(facc - zx*WSUM[n]) ----------
#pragma unroll
    for (int mf = 0; mf < 4; mf++) {
        const int m_lo = m0 + wm * 64 + mf * 16 + (lane >> 2);
        const int m_hi = m_lo + 8;
        const float sx0 = g_SX[m_lo], zx0 = g_ZX[m_lo];
        const float sx1 = g_SX[m_hi], zx1 = g_ZX[m_hi];
        float* row_lo = out + (size_t)m_lo * NDIM + n0 + wn * 32 + ncol2;
        float* row_hi = out + (size_t)m_hi * NDIM + n0 + wn * 32 + ncol2;
#pragma unroll
        for (int nf = 0; nf < 4; nf++) {
            const int ng = n0 + wn * 32 + nf * 8 + ncol2;
            const float ws0 = g_WSUM[ng];
            const float ws1 = g_WSUM[ng + 1];
            float2 v0, v1;
            v0.x = sx0 * (facc[mf][nf][0] - zx0 * ws0);
            v0.y = sx0 * (facc[mf][nf][1] - zx0 * ws1);
            v1.x = sx1 * (facc[mf][nf][2] - zx1 * ws0);
            v1.y = sx1 * (facc[mf][nf][3] - zx1 * ws1);
            *(float2*)(row_lo + nf * 8) = v0;
            *(float2*)(row_hi + nf * 8) = v1;
        }
    }
}

// ============================================================
// Launcher
// ============================================================
extern "C" void kernel_launch(void* const* d_in, const int* in_sizes, int n_in,
                              void* d_out, int out_size) {
    const float* x = (const float*)d_in[0];   // [4, 2048, 4096] fp32
    const float* w = (const float*)d_in[1];   // [4096, 4096] fp32
    float* out = (float*)d_out;               // [4, 2048, 4096] fp32

    cudaFuncSetAttribute(gemm_kernel, cudaFuncAttributeMaxDynamicSharedMemorySize, GEMM_SMEM);

    w_quant_kernel<<<4096, 256>>>(w);         // 131072 groups / 32 per block
    wsum_kernel<<<512, 256>>>();              // 4096 rows / 8 per block
    act_quant_kernel<<<MROWS, 256>>>(x);
    gemm_kernel<<<dim3(NDIM / TN, MROWS / TM), THREADS, GEMM_SMEM>>>(out);
}

// round 13
// speedup vs baseline: 1.1619x; 1.0067x over previous
#include <cuda_runtime.h>
#include <cstdint>
#include <cstddef>

// ============================================================
// Problem dims (fixed)
// ============================================================
#define MROWS 8192
#define NDIM  4096
#define KDIM  4096
#define KGROUPS 32                   // 4096 / 128 quant groups per row

// GEMM tiling: CTA 128x128, 8 warps (2 M x 4 N), warp tile 64x32  (measured best)
#define TM 128
#define TN 128
#define KB 128                       // K int8 per stage = ONE quant group
#define NKB (KDIM / KB)              // 32
#define NSTAGES 4
#define A_BYTES (TM * 128)           // 16384
#define B_BYTES (TN * 128)           // 16384
#define STAGE_BYTES (A_BYTES + B_BYTES)            // 32768
#define SW_BYTES (KGROUPS * TN * 4)                // 16384 group scales in SMEM
#define GEMM_SMEM (SW_BYTES + NSTAGES * STAGE_BYTES)   // 147456

#define THREADS 256                  // 8 warps

// Fused quant kernel grid split
#define WQ_BLOCKS 4096               // 131072 groups / 32 per block
#define AQ_BLOCKS MROWS              // one row per block
#define FUSED_BLOCKS (WQ_BLOCKS + AQ_BLOCKS)

// ============================================================
// Scratch (static __device__ — no runtime allocation)
// ============================================================
__device__ signed char g_XQ[(size_t)MROWS * KDIM];   // 32 MB: qx int8 (exact)
__device__ signed char g_WQ[(size_t)NDIM * KDIM];    // 16 MB: wq = (q - z) in [0,15]
__device__ float g_SX[MROWS];                        // activation scale per row
__device__ float g_ZX[MROWS];                        // activation zero per row
__device__ float g_WS[(size_t)NDIM * KGROUPS];       // weight group scale sw[n][g]
__device__ float g_WGS[(size_t)NDIM * KGROUPS];      // sw[n][g] * sum_{k in g} wq
__device__ float g_WSUM[NDIM];                       // sum_k w_deq[n][k]

// ============================================================
// PTX helpers (sm_100 baseline ISA — no 'a'-suffix features)
// ============================================================
__device__ __forceinline__ uint32_t smem_u32(const void* p) {
    uint32_t a;
    asm("{ .reg .u64 t; cvta.to.shared.u64 t, %1; cvt.u32.u64 %0, t; }" : "=r"(a) : "l"(p));
    return a;
}

#define CP16(smem_addr, gptr) \
    asm volatile("cp.async.cg.shared.global [%0], [%1], 16;" :: "r"(smem_addr), "l"(gptr) : "memory")
#define CP_COMMIT()  asm volatile("cp.async.commit_group;" ::: "memory")
#define CP_WAIT2()   asm volatile("cp.async.wait_group 2;" ::: "memory")
#define CP_WAIT0()   asm volatile("cp.async.wait_group 0;" ::: "memory")

#define LDSM_X4(r0, r1, r2, r3, addr)                                        \
    asm volatile("ldmatrix.sync.aligned.m8n8.x4.shared.b16 {%0,%1,%2,%3}, [%4];" \
                 : "=r"(r0), "=r"(r1), "=r"(r2), "=r"(r3) : "r"(addr))

#define MMAS8(c, a, b0, b1)                                                  \
    asm volatile("mma.sync.aligned.m16n8k32.row.col.s32.s8.s8.s32 "          \
                 "{%0,%1,%2,%3}, {%4,%5,%6,%7}, {%8,%9}, {%0,%1,%2,%3};"     \
                 : "+r"((c)[0]), "+r"((c)[1]), "+r"((c)[2]), "+r"((c)[3])    \
                 : "r"((a)[0]), "r"((a)[1]), "r"((a)[2]), "r"((a)[3]),       \
                   "r"((b0)), "r"((b1)))

// Stage load: A rows {r0,+32,+64,+96}, B rows same; one 16B chunk/row/thread.
#define LOAD_STAGE(kb)                                                        \
    do {                                                                      \
        const uint32_t so_ = (uint32_t)((kb) & (NSTAGES - 1)) * STAGE_BYTES;  \
        const signed char* pA = gA + (size_t)(kb) * 128;                      \
        const signed char* pB = gB + (size_t)(kb) * 128;                      \
        CP16(smA + so_,            pA);                                       \
        CP16(smA + so_ + 32 * 128, pA + (size_t)32 * KDIM);                   \
        CP16(smA + so_ + 64 * 128, pA + (size_t)64 * KDIM);                   \
        CP16(smA + so_ + 96 * 128, pA + (size_t)96 * KDIM);                   \
        CP16(smB + so_,            pB);                                       \
        CP16(smB + so_ + 32 * 128, pB + (size_t)32 * KDIM);                   \
        CP16(smB + so_ + 64 * 128, pB + (size_t)64 * KDIM);                   \
        CP16(smB + so_ + 96 * 128, pB + (size_t)96 * KDIM);                   \
        CP_COMMIT();                                                          \
    } while (0)

// ============================================================
// Kernel 1 (FUSED): weight group quant + activation row quant.
//   blocks [0, WQ_BLOCKS):            32 weight groups per block (4/warp, MLP=4)
//   blocks [WQ_BLOCKS, FUSED_BLOCKS): one activation row per block
// The two passes are independent; fusing overlaps their HBM streams and
// removes one launch boundary.
// ============================================================
__global__ void __launch_bounds__(256) fused_quant_kernel(
    const float* __restrict__ x, const float* __restrict__ w) {
    if (blockIdx.x < WQ_BLOCKS) {
        // ---------------- weight group quant (gs=128, nbit=4, asym) ----------------
        int gbase = blockIdx.x * 32 + (threadIdx.x >> 5) * 4;   // 4 groups per warp
        int lane  = threadIdx.x & 31;

        float4 f[4];
#pragma unroll
        for (int i = 0; i < 4; i++)
            f[i] = ((const float4*)(w + (size_t)(gbase + i) * 128))[lane];

#pragma unroll
        for (int i = 0; i < 4; i++) {
            int g = gbase + i;
            float v[4] = {f[i].x, f[i].y, f[i].z, f[i].w};
            float mn = fminf(fminf(v[0], v[1]), fminf(v[2], v[3]));
            float mx = fmaxf(fmaxf(v[0], v[1]), fmaxf(v[2], v[3]));
#pragma unroll
            for (int off = 16; off > 0; off >>= 1) {
                mn = fminf(mn, __shfl_xor_sync(0xffffffffu, mn, off));
                mx = fmaxf(mx, __shfl_xor_sync(0xffffffffu, mx, off));
            }
            float sc = __fdiv_rn(mx - mn, 15.0f);
            if (!(sc > 0.0f)) sc = 1.0f;
            float z = -8.0f - rintf(__fdiv_rn(mn, sc));

            float gsum = 0.0f;
            signed char o[4];
#pragma unroll
            for (int j = 0; j < 4; j++) {
                float q = rintf(__fdiv_rn(v[j], sc)) + z;
                q = fminf(fmaxf(q, -8.0f), 7.0f);
                float wq = q - z;             // exact small integer in [0,15]
                gsum += wq;
                o[j] = (signed char)__float2int_rn(wq);
            }
            ((char4*)(g_WQ + (size_t)g * 128))[lane] = make_char4(o[0], o[1], o[2], o[3]);
#pragma unroll
            for (int off = 16; off > 0; off >>= 1)
                gsum += __shfl_xor_sync(0xffffffffu, gsum, off);
            if (lane == 0) {
                g_WS[g]  = sc;
                g_WGS[g] = sc * gsum;
            }
        }
    } else {
        // ---------------- activation dynamic per-row int8 quant ----------------
        int row = blockIdx.x - WQ_BLOCKS;
        int tid = threadIdx.x;
        const float4* xr4 = (const float4*)(x + (size_t)row * KDIM);

        float vals[16];
        float mn = 3.4e38f, mx = -3.4e38f;
#pragma unroll
        for (int j = 0; j < 4; j++) {
            float4 f = xr4[tid + j * 256];
            vals[4 * j + 0] = f.x; vals[4 * j + 1] = f.y;
            vals[4 * j + 2] = f.z; vals[4 * j + 3] = f.w;
            mn = fminf(mn, fminf(fminf(f.x, f.y), fminf(f.z, f.w)));
            mx = fmaxf(mx, fmaxf(fmaxf(f.x, f.y), fmaxf(f.z, f.w)));
        }
#pragma unroll
        for (int off = 16; off > 0; off >>= 1) {
            mn = fminf(mn, __shfl_xor_sync(0xffffffffu, mn, off));
            mx = fmaxf(mx, __shfl_xor_sync(0xffffffffu, mx, off));
        }
        __shared__ float smin[8], smax[8];
        __shared__ float s_sc, s_z;
        if ((tid & 31) == 0) { smin[tid >> 5] = mn; smax[tid >> 5] = mx; }
        __syncthreads();
        if (tid == 0) {
            float rmn = smin[0], rmx = smax[0];
#pragma unroll
            for (int i = 1; i < 8; i++) { rmn = fminf(rmn, smin[i]); rmx = fmaxf(rmx, smax[i]); }
            float sc = __fdiv_rn(rmx - rmn, 255.0f);
            if (!(sc > 0.0f)) sc = 1.0f;
            float z = -128.0f - rintf(__fdiv_rn(rmn, sc));
            s_sc = sc; s_z = z;
            g_SX[row] = sc;
            g_ZX[row] = z;
        }
        __syncthreads();
        float sc = s_sc, z = s_z;
        char4* outp4 = (char4*)(g_XQ + (size_t)row * KDIM);
#pragma unroll
        for (int j = 0; j < 4; j++) {
            signed char o[4];
#pragma unroll
            for (int e = 0; e < 4; e++) {
                float q = rintf(__fdiv_rn(vals[4 * j + e], sc)) + z;
                q = fminf(fmaxf(q, -128.0f), 127.0f);
                o[e] = (signed char)__float2int_rn(q);
            }
            outp4[tid + j * 256] = make_char4(o[0], o[1], o[2], o[3]);
        }
    }
}

// ============================================================
// Kernel 1b: WSUM[n] = sum_g g_WGS[n*32+g]
// ============================================================
__global__ void __launch_bounds__(256) wsum_kernel() {
    int n    = blockIdx.x * 8 + (threadIdx.x >> 5);
    int lane = threadIdx.x & 31;
    float v = g_WGS[(size_t)n * KGROUPS + lane];
#pragma unroll
    for (int off = 16; off > 0; off >>= 1)
        v += __shfl_xor_sync(0xffffffffu, v, off);
    if (lane == 0) g_WSUM[n] = v;
}

// ============================================================
// Kernel 2: int8 IMMA GEMM — measured-best configuration (527.5 us)
// CTA 128x128, 8 warps (2 M x 4 N), warp tile 64x32; K-stage = 1 group.
// 4-stage cp.async ring; uniform tail commits (provable stage completion).
//   y[m,n] = sx_m * ( sum_g sw[n,g]*S1_g[m,n] ) - sx_m*zx_m*WSUM[n]
//   S1_g exact int32 (|.| < 2^22 -> exact I2F).
// ============================================================
__global__ void __launch_bounds__(THREADS, 1)
gemm_kernel(float* __restrict__ out) {
    extern __shared__ char smem[];
    const uint32_t swbase = smem_u32(smem);          // [32 g][128 n] fp32 = 16 KB
    const uint32_t tiles  = swbase + SW_BYTES;

    const int tid  = threadIdx.x;
    const int wid  = tid >> 5;
    const int lane = tid & 31;
    const int wm   = wid & 1;        // 0..1  (M)
    const int wn   = wid >> 1;       // 0..3  (N)

    const int m0 = blockIdx.y * TM;
    const int n0 = blockIdx.x * TN;

    // ---------- producer addressing ----------
    const int  r0  = tid >> 3;       // 0..31
    const int  c   = tid & 7;        // 16B chunk within 128B row
    const uint32_t swz = (uint32_t)(((c ^ (r0 & 7)) & 7) * 16);

    const signed char* gA = g_XQ + (size_t)(m0 + r0) * KDIM + c * 16;
    const signed char* gB = g_WQ + (size_t)(n0 + r0) * KDIM + c * 16;
    const uint32_t smA = tiles + (uint32_t)r0 * 128 + swz;
    const uint32_t smB = tiles + A_BYTES + (uint32_t)r0 * 128 + swz;

    // ---------- prologue: 3 stages in flight (issued FIRST so the scale
    // staging LDGs below overlap with cp.async flight time) ----------
    LOAD_STAGE(0);
    LOAD_STAGE(1);
    LOAD_STAGE(2);

    // ---------- stage the group scales: sw_s[g][n] = g_WS[(n0+n)*32 + g] ----------
    for (int idx = tid; idx < KGROUPS * TN; idx += THREADS) {
        int n = idx >> 5;            // g contiguous in gmem -> coalesced LDG
        int g = idx & 31;
        ((float*)smem)[g * TN + n] = g_WS[(size_t)(n0 + n) * KGROUPS + g];
    }

    // ---------- consumer (ldmatrix) addressing ----------
    const uint32_t xr = (uint32_t)((lane & 7) * 16);
    // A x4 (m16 x k32): rows wm*64 + mf*16 + (lane&7) + ((lane>>3)&1)*8
    const uint32_t adA0 = tiles +
        (uint32_t)(wm * 64 + (lane & 7) + ((lane >> 3) & 1) * 8) * 128;
    const uint32_t ach = (uint32_t)((lane >> 4) * 16);
    // B x4 (2 n-frags x k32): rows wn*32 + g*16 + (lane&7) + (lane>>4)*8
    const uint32_t adB0 = tiles + A_BYTES +
        (uint32_t)(wn * 32 + (lane & 7) + (lane >> 4) * 8) * 128;
    const uint32_t bch = (uint32_t)(((lane >> 3) & 1) * 16);

    float facc[4][4][4];
#pragma unroll
    for (int i = 0; i < 4; i++)
#pragma unroll
        for (int j = 0; j < 4; j++)
#pragma unroll
            for (int q = 0; q < 4; q++) facc[i][j][q] = 0.0f;

    const int ncol2 = (lane & 3) * 2;

    // ---------- main loop: one quant group per iteration ----------
    for (int kb = 0; kb < NKB; kb++) {
        // Commits issued before this wait: 3 + kb (uniform, incl. tail).
        // wait<=2 pending => >= kb+1 complete => stage kb's commit done.
        CP_WAIT2();
        __syncthreads();

        // next stage's global loads; empty commit in tail keeps count uniform
        if (kb + 3 < NKB) { LOAD_STAGE(kb + 3); } else { CP_COMMIT(); }

        const uint32_t so = (uint32_t)(kb & (NSTAGES - 1)) * STAGE_BYTES;

        // group scales for this thread's 8 n-columns
        float swr[8];
        {
            const float* swp = (const float*)smem + (size_t)kb * TN + wn * 32 + ncol2;
#pragma unroll
            for (int nf = 0; nf < 4; nf++) {
                float2 s2 = *(const float2*)(swp + nf * 8);
                swr[2 * nf]     = s2.x;
                swr[2 * nf + 1] = s2.y;
            }
        }

        // B fragments for all 4 k-steps
        uint32_t bu[4][8];
#pragma unroll
        for (int ks = 0; ks < 4; ks++) {
            const uint32_t kc = (uint32_t)(ks * 32);
            LDSM_X4(bu[ks][0], bu[ks][1], bu[ks][2], bu[ks][3],
                    adB0 + so + ((kc + bch) ^ xr));
            LDSM_X4(bu[ks][4], bu[ks][5], bu[ks][6], bu[ks][7],
                    adB0 + 2048 + so + ((kc + bch) ^ xr));
        }

#pragma unroll
        for (int mf = 0; mf < 4; mf++) {
            int ic[4][4];
#pragma unroll
            for (int nf = 0; nf < 4; nf++)
#pragma unroll
                for (int q = 0; q < 4; q++) ic[nf][q] = 0;

#pragma unroll
            for (int ks = 0; ks < 4; ks++) {
                const uint32_t kc = (uint32_t)(ks * 32);
                uint32_t a[4];
                LDSM_X4(a[0], a[1], a[2], a[3],
                        adA0 + (uint32_t)mf * 2048 + so + ((kc + ach) ^ xr));
#pragma unroll
                for (int nf = 0; nf < 4; nf++)
                    MMAS8(ic[nf], a, bu[ks][2 * nf], bu[ks][2 * nf + 1]);
            }
            // fold group: facc += sw * S1  (I2F exact: |S1| < 2^22)
#pragma unroll
            for (int nf = 0; nf < 4; nf++) {
                facc[mf][nf][0] += __int2float_rn(ic[nf][0]) * swr[2 * nf];
                facc[mf][nf][1] += __int2float_rn(ic[nf][1]) * swr[2 * nf + 1];
                facc[mf][nf][2] += __int2float_rn(ic[nf][2]) * swr[2 * nf];
                facc[mf][nf][3] += __int2float_rn(ic[nf][3]) * swr[2 * nf + 1];
            }
        }
        __syncthreads();
    }
    CP_WAIT0();

    // ---------- epilogue: y = sx*(facc - zx*WSUM[n]) ----------
#pragma unroll
    for (int mf = 0; mf < 4; mf++) {
        const int m_lo = m0 + wm * 64 + mf * 16 + (lane >> 2);
        const int m_hi = m_lo + 8;
        const float sx0 = g_SX[m_lo], zx0 = g_ZX[m_lo];
        const float sx1 = g_SX[m_hi], zx1 = g_ZX[m_hi];
        float* row_lo = out + (size_t)m_lo * NDIM + n0 + wn * 32 + ncol2;
        float* row_hi = out + (size_t)m_hi * NDIM + n0 + wn * 32 + ncol2;
#pragma unroll
        for (int nf = 0; nf < 4; nf++) {
            const int ng = n0 + wn * 32 + nf * 8 + ncol2;
            const float ws0 = g_WSUM[ng];
            const float ws1 = g_WSUM[ng + 1];
            float2 v0, v1;
            v0.x = sx0 * (facc[mf][nf][0] - zx0 * ws0);
            v0.y = sx0 * (facc[mf][nf][1] - zx0 * ws1);
            v1.x = sx1 * (facc[mf][nf][2] - zx1 * ws0);
            v1.y = sx1 * (facc[mf][nf][3] - zx1 * ws1);
            *(float2*)(row_lo + nf * 8) = v0;
            *(float2*)(row_hi + nf * 8) = v1;
        }
    }
}

// ============================================================
// Launcher
// ============================================================
extern "C" void kernel_launch(void* const* d_in, const int* in_sizes, int n_in,
                              void* d_out, int out_size) {
    const float* x = (const float*)d_in[0];   // [4, 2048, 4096] fp32
    const float* w = (const float*)d_in[1];   // [4096, 4096] fp32
    float* out = (float*)d_out;               // [4, 2048, 4096] fp32

    cudaFuncSetAttribute(gemm_kernel, cudaFuncAttributeMaxDynamicSharedMemorySize, GEMM_SMEM);

    fused_quant_kernel<<<FUSED_BLOCKS, 256>>>(x, w);  // weights + activations together
    wsum_kernel<<<512, 256>>>();                      // 4096 rows / 8 per block
    gemm_kernel<<<dim3(NDIM / TN, MROWS / TM), THREADS, GEMM_SMEM>>>(out);
}

// round 14
// speedup vs baseline: 1.1872x; 1.0218x over previous
#include <cuda_runtime.h>
#include <cstdint>
#include <cstddef>

// ============================================================
// Problem dims (fixed)
// ============================================================
#define MROWS 8192
#define NDIM  4096
#define KDIM  4096
#define KGROUPS 32                   // 4096 / 128 quant groups per row

// GEMM tiling: CTA 128x128, 8 warps (2 M x 4 N), warp tile 64x32  (measured best)
#define TM 128
#define TN 128
#define KB 128                       // K int8 per stage = ONE quant group
#define NKB (KDIM / KB)              // 32
#define NSTAGES 4
#define A_BYTES (TM * 128)           // 16384
#define B_BYTES (TN * 128)           // 16384
#define STAGE_BYTES (A_BYTES + B_BYTES)            // 32768
#define SW_BYTES (KGROUPS * TN * 4)                // 16384 group scales in SMEM
#define GEMM_SMEM (SW_BYTES + NSTAGES * STAGE_BYTES)   // 147456

#define THREADS 256                  // 8 warps

// Fused quant kernel grid split
#define WQ_BLOCKS 4096               // 131072 groups / 32 per block
#define AQ_BLOCKS MROWS              // one row per block
#define FUSED_BLOCKS (WQ_BLOCKS + AQ_BLOCKS)

// ============================================================
// Scratch (static __device__ — no runtime allocation)
// ============================================================
__device__ signed char g_XQ[(size_t)MROWS * KDIM];   // 32 MB: qx int8 (exact)
__device__ signed char g_WQ[(size_t)NDIM * KDIM];    // 16 MB: wq = (q - z) in [0,15]
__device__ float g_SX[MROWS];                        // activation scale per row
__device__ float g_ZX[MROWS];                        // activation zero per row
__device__ float g_WS[(size_t)NDIM * KGROUPS];       // weight group scale sw[n][g]
__device__ float g_WGS[(size_t)NDIM * KGROUPS];      // sw[n][g] * sum_{k in g} wq
__device__ float g_WSUM[NDIM];                       // sum_k w_deq[n][k]

// ============================================================
// PTX helpers (sm_100 baseline ISA — no 'a'-suffix features)
// ============================================================
__device__ __forceinline__ uint32_t smem_u32(const void* p) {
    uint32_t a;
    asm("{ .reg .u64 t; cvta.to.shared.u64 t, %1; cvt.u32.u64 %0, t; }" : "=r"(a) : "l"(p));
    return a;
}

#define CP16(smem_addr, gptr) \
    asm volatile("cp.async.cg.shared.global [%0], [%1], 16;" :: "r"(smem_addr), "l"(gptr) : "memory")
#define CP_COMMIT()  asm volatile("cp.async.commit_group;" ::: "memory")
#define CP_WAIT2()   asm volatile("cp.async.wait_group 2;" ::: "memory")
#define CP_WAIT0()   asm volatile("cp.async.wait_group 0;" ::: "memory")

#define LDSM_X4(r0, r1, r2, r3, addr)                                        \
    asm volatile("ldmatrix.sync.aligned.m8n8.x4.shared.b16 {%0,%1,%2,%3}, [%4];" \
                 : "=r"(r0), "=r"(r1), "=r"(r2), "=r"(r3) : "r"(addr))

#define MMAS8(c, a, b0, b1)                                                  \
    asm volatile("mma.sync.aligned.m16n8k32.row.col.s32.s8.s8.s32 "          \
                 "{%0,%1,%2,%3}, {%4,%5,%6,%7}, {%8,%9}, {%0,%1,%2,%3};"     \
                 : "+r"((c)[0]), "+r"((c)[1]), "+r"((c)[2]), "+r"((c)[3])    \
                 : "r"((a)[0]), "r"((a)[1]), "r"((a)[2]), "r"((a)[3]),       \
                   "r"((b0)), "r"((b1)))

// Stage load: A rows {r0,+32,+64,+96}, B rows same; one 16B chunk/row/thread.
#define LOAD_STAGE(kb)                                                        \
    do {                                                                      \
        const uint32_t so_ = (uint32_t)((kb) & (NSTAGES - 1)) * STAGE_BYTES;  \
        const signed char* pA = gA + (size_t)(kb) * 128;                      \
        const signed char* pB = gB + (size_t)(kb) * 128;                      \
        CP16(smA + so_,            pA);                                       \
        CP16(smA + so_ + 32 * 128, pA + (size_t)32 * KDIM);                   \
        CP16(smA + so_ + 64 * 128, pA + (size_t)64 * KDIM);                   \
        CP16(smA + so_ + 96 * 128, pA + (size_t)96 * KDIM);                   \
        CP16(smB + so_,            pB);                                       \
        CP16(smB + so_ + 32 * 128, pB + (size_t)32 * KDIM);                   \
        CP16(smB + so_ + 64 * 128, pB + (size_t)64 * KDIM);                   \
        CP16(smB + so_ + 96 * 128, pB + (size_t)96 * KDIM);                   \
        CP_COMMIT();                                                          \
    } while (0)

// ============================================================
// Kernel 1 (FUSED): weight group quant + activation row quant.
//   blocks [0, WQ_BLOCKS):            32 weight groups per block (4/warp, MLP=4)
//   blocks [WQ_BLOCKS, FUSED_BLOCKS): one activation row per block
// Per-element division replaced by multiply with once-per-group
// correctly-rounded reciprocal (kills the ~10-instr fdiv sequence that made
// this kernel issue-bound at 49.5% HBM).
// ============================================================
__global__ void __launch_bounds__(256) fused_quant_kernel(
    const float* __restrict__ x, const float* __restrict__ w) {
    if (blockIdx.x < WQ_BLOCKS) {
        // ---------------- weight group quant (gs=128, nbit=4, asym) ----------------
        int gbase = blockIdx.x * 32 + (threadIdx.x >> 5) * 4;   // 4 groups per warp
        int lane  = threadIdx.x & 31;

        float4 f[4];
#pragma unroll
        for (int i = 0; i < 4; i++)
            f[i] = ((const float4*)(w + (size_t)(gbase + i) * 128))[lane];

#pragma unroll
        for (int i = 0; i < 4; i++) {
            int g = gbase + i;
            float v[4] = {f[i].x, f[i].y, f[i].z, f[i].w};
            float mn = fminf(fminf(v[0], v[1]), fminf(v[2], v[3]));
            float mx = fmaxf(fmaxf(v[0], v[1]), fmaxf(v[2], v[3]));
#pragma unroll
            for (int off = 16; off > 0; off >>= 1) {
                mn = fminf(mn, __shfl_xor_sync(0xffffffffu, mn, off));
                mx = fmaxf(mx, __shfl_xor_sync(0xffffffffu, mx, off));
            }
            float sc = __fdiv_rn(mx - mn, 15.0f);
            if (!(sc > 0.0f)) sc = 1.0f;
            float z   = -8.0f - rintf(__fdiv_rn(mn, sc));   // once per group: exact
            float inv = __fdiv_rn(1.0f, sc);                // once per group

            float gsum = 0.0f;
            signed char o[4];
#pragma unroll
            for (int j = 0; j < 4; j++) {
                float q = rintf(v[j] * inv) + z;
                q = fminf(fmaxf(q, -8.0f), 7.0f);
                float wq = q - z;             // exact small integer in [0,15]
                gsum += wq;
                o[j] = (signed char)__float2int_rn(wq);
            }
            ((char4*)(g_WQ + (size_t)g * 128))[lane] = make_char4(o[0], o[1], o[2], o[3]);
#pragma unroll
            for (int off = 16; off > 0; off >>= 1)
                gsum += __shfl_xor_sync(0xffffffffu, gsum, off);
            if (lane == 0) {
                g_WS[g]  = sc;
                g_WGS[g] = sc * gsum;
            }
        }
    } else {
        // ---------------- activation dynamic per-row int8 quant ----------------
        int row = blockIdx.x - WQ_BLOCKS;
        int tid = threadIdx.x;
        const float4* xr4 = (const float4*)(x + (size_t)row * KDIM);

        float vals[16];
        float mn = 3.4e38f, mx = -3.4e38f;
#pragma unroll
        for (int j = 0; j < 4; j++) {
            float4 f = xr4[tid + j * 256];
            vals[4 * j + 0] = f.x; vals[4 * j + 1] = f.y;
            vals[4 * j + 2] = f.z; vals[4 * j + 3] = f.w;
            mn = fminf(mn, fminf(fminf(f.x, f.y), fminf(f.z, f.w)));
            mx = fmaxf(mx, fmaxf(fmaxf(f.x, f.y), fmaxf(f.z, f.w)));
        }
#pragma unroll
        for (int off = 16; off > 0; off >>= 1) {
            mn = fminf(mn, __shfl_xor_sync(0xffffffffu, mn, off));
            mx = fmaxf(mx, __shfl_xor_sync(0xffffffffu, mx, off));
        }
        __shared__ float smin[8], smax[8];
        __shared__ float s_sc, s_z, s_inv;
        if ((tid & 31) == 0) { smin[tid >> 5] = mn; smax[tid >> 5] = mx; }
        __syncthreads();
        if (tid == 0) {
            float rmn = smin[0], rmx = smax[0];
#pragma unroll
            for (int i = 1; i < 8; i++) { rmn = fminf(rmn, smin[i]); rmx = fmaxf(rmx, smax[i]); }
            float sc = __fdiv_rn(rmx - rmn, 255.0f);
            if (!(sc > 0.0f)) sc = 1.0f;
            float z = -128.0f - rintf(__fdiv_rn(rmn, sc));  // once per row: exact
            s_sc = sc; s_z = z;
            s_inv = __fdiv_rn(1.0f, sc);                    // once per row
            g_SX[row] = sc;
            g_ZX[row] = z;
        }
        __syncthreads();
        float inv = s_inv, z = s_z;
        char4* outp4 = (char4*)(g_XQ + (size_t)row * KDIM);
#pragma unroll
        for (int j = 0; j < 4; j++) {
            signed char o[4];
#pragma unroll
            for (int e = 0; e < 4; e++) {
                float q = rintf(vals[4 * j + e] * inv) + z;
                q = fminf(fmaxf(q, -128.0f), 127.0f);
                o[e] = (signed char)__float2int_rn(q);
            }
            outp4[tid + j * 256] = make_char4(o[0], o[1], o[2], o[3]);
        }
    }
}

// ============================================================
// Kernel 1b: WSUM[n] = sum_g g_WGS[n*32+g]
// ============================================================
__global__ void __launch_bounds__(256) wsum_kernel() {
    int n    = blockIdx.x * 8 + (threadIdx.x >> 5);
    int lane = threadIdx.x & 31;
    float v = g_WGS[(size_t)n * KGROUPS + lane];
#pragma unroll
    for (int off = 16; off > 0; off >>= 1)
        v += __shfl_xor_sync(0xffffffffu, v, off);
    if (lane == 0) g_WSUM[n] = v;
}

// ============================================================
// Kernel 2: int8 IMMA GEMM — measured-best configuration (527.5 us)
// CTA 128x128, 8 warps (2 M x 4 N), warp tile 64x32; K-stage = 1 group.
// 4-stage cp.async ring; uniform tail commits (provable stage completion).
//   y[m,n] = sx_m * ( sum_g sw[n,g]*S1_g[m,n] ) - sx_m*zx_m*WSUM[n]
//   S1_g exact int32 (|.| < 2^22 -> exact I2F).
// ============================================================
__global__ void __launch_bounds__(THREADS, 1)
gemm_kernel(float* __restrict__ out) {
    extern __shared__ char smem[];
    const uint32_t swbase = smem_u32(smem);          // [32 g][128 n] fp32 = 16 KB
    const uint32_t tiles  = swbase + SW_BYTES;

    const int tid  = threadIdx.x;
    const int wid  = tid >> 5;
    const int lane = tid & 31;
    const int wm   = wid & 1;        // 0..1  (M)
    const int wn   = wid >> 1;       // 0..3  (N)

    const int m0 = blockIdx.y * TM;
    const int n0 = blockIdx.x * TN;

    // ---------- producer addressing ----------
    const int  r0  = tid >> 3;       // 0..31
    const int  c   = tid & 7;        // 16B chunk within 128B row
    const uint32_t swz = (uint32_t)(((c ^ (r0 & 7)) & 7) * 16);

    const signed char* gA = g_XQ + (size_t)(m0 + r0) * KDIM + c * 16;
    const signed char* gB = g_WQ + (size_t)(n0 + r0) * KDIM + c * 16;
    const uint32_t smA = tiles + (uint32_t)r0 * 128 + swz;
    const uint32_t smB = tiles + A_BYTES + (uint32_t)r0 * 128 + swz;

    // ---------- prologue: 3 stages in flight (issued FIRST so the scale
    // staging LDGs below overlap with cp.async flight time) ----------
    LOAD_STAGE(0);
    LOAD_STAGE(1);
    LOAD_STAGE(2);

    // ---------- stage the group scales: sw_s[g][n] = g_WS[(n0+n)*32 + g] ----------
    for (int idx = tid; idx < KGROUPS * TN; idx += THREADS) {
        int n = idx >> 5;            // g contiguous in gmem -> coalesced LDG
        int g = idx & 31;
        ((float*)smem)[g * TN + n] = g_WS[(size_t)(n0 + n) * KGROUPS + g];
    }

    // ---------- consumer (ldmatrix) addressing ----------
    const uint32_t xr = (uint32_t)((lane & 7) * 16);
    // A x4 (m16 x k32): rows wm*64 + mf*16 + (lane&7) + ((lane>>3)&1)*8
    const uint32_t adA0 = tiles +
        (uint32_t)(wm * 64 + (lane & 7) + ((lane >> 3) & 1) * 8) * 128;
    const uint32_t ach = (uint32_t)((lane >> 4) * 16);
    // B x4 (2 n-frags x k32): rows wn*32 + g*16 + (lane&7) + (lane>>4)*8
    const uint32_t adB0 = tiles + A_BYTES +
        (uint32_t)(wn * 32 + (lane & 7) + (lane >> 4) * 8) * 128;
    const uint32_t bch = (uint32_t)(((lane >> 3) & 1) * 16);

    float facc[4][4][4];
#pragma unroll
    for (int i = 0; i < 4; i++)
#pragma unroll
        for (int j = 0; j < 4; j++)
#pragma unroll
            for (int q = 0; q < 4; q++) facc[i][j][q] = 0.0f;

    const int ncol2 = (lane & 3) * 2;

    // ---------- main loop: one quant group per iteration ----------
    for (int kb = 0; kb < NKB; kb++) {
        // Commits issued before this wait: 3 + kb (uniform, incl. tail).
        // wait<=2 pending => >= kb+1 complete => stage kb's commit done.
        CP_WAIT2();
        __syncthreads();

        // next stage's global loads; empty commit in tail keeps count uniform
        if (kb + 3 < NKB) { LOAD_STAGE(kb + 3); } else { CP_COMMIT(); }

        const uint32_t so = (uint32_t)(kb & (NSTAGES - 1)) * STAGE_BYTES;

        // group scales for this thread's 8 n-columns
        float swr[8];
        {
            const float* swp = (const float*)smem + (size_t)kb * TN + wn * 32 + ncol2;
#pragma unroll
            for (int nf = 0; nf < 4; nf++) {
                float2 s2 = *(const float2*)(swp + nf * 8);
                swr[2 * nf]     = s2.x;
                swr[2 * nf + 1] = s2.y;
            }
        }

        // B fragments for all 4 k-steps
        uint32_t bu[4][8];
#pragma unroll
        for (int ks = 0; ks < 4; ks++) {
            const uint32_t kc = (uint32_t)(ks * 32);
            LDSM_X4(bu[ks][0], bu[ks][1], bu[ks][2], bu[ks][3],
                    adB0 + so + ((kc + bch) ^ xr));
            LDSM_X4(bu[ks][4], bu[ks][5], bu[ks][6], bu[ks][7],
                    adB0 + 2048 + so + ((kc + bch) ^ xr));
        }

#pragma unroll
        for (int mf = 0; mf < 4; mf++) {
            int ic[4][4];
#pragma unroll
            for (int nf = 0; nf < 4; nf++)
#pragma unroll
                for (int q = 0; q < 4; q++) ic[nf][q] = 0;

#pragma unroll
            for (int ks = 0; ks < 4; ks++) {
                const uint32_t kc = (uint32_t)(ks * 32);
                uint32_t a[4];
                LDSM_X4(a[0], a[1], a[2], a[3],
                        adA0 + (uint32_t)mf * 2048 + so + ((kc + ach) ^ xr));
#pragma unroll
                for (int nf = 0; nf < 4; nf++)
                    MMAS8(ic[nf], a, bu[ks][2 * nf], bu[ks][2 * nf + 1]);
            }
            // fold group: facc += sw * S1  (I2F exact: |S1| < 2^22)
#pragma unroll
            for (int nf = 0; nf < 4; nf++) {
                facc[mf][nf][0] += __int2float_rn(ic[nf][0]) * swr[2 * nf];
                facc[mf][nf][1] += __int2float_rn(ic[nf][1]) * swr[2 * nf + 1];
                facc[mf][nf][2] += __int2float_rn(ic[nf][2]) * swr[2 * nf];
                facc[mf][nf][3] += __int2float_rn(ic[nf][3]) * swr[2 * nf + 1];
            }
        }
        __syncthreads();
    }
    CP_WAIT0();

    // ---------- epilogue: y = sx*(facc - zx*WSUM[n]) ----------
#pragma unroll
    for (int mf = 0; mf < 4; mf++) {
        const int m_lo = m0 + wm * 64 + mf * 16 + (lane >> 2);
        const int m_hi = m_lo + 8;
        const float sx0 = g_SX[m_lo], zx0 = g_ZX[m_lo];
        const float sx1 = g_SX[m_hi], zx1 = g_ZX[m_hi];
        float* row_lo = out + (size_t)m_lo * NDIM + n0 + wn * 32 + ncol2;
        float* row_hi = out + (size_t)m_hi * NDIM + n0 + wn * 32 + ncol2;
#pragma unroll
        for (int nf = 0; nf < 4; nf++) {
            const int ng = n0 + wn * 32 + nf * 8 + ncol2;
            const float ws0 = g_WSUM[ng];
            const float ws1 = g_WSUM[ng + 1];
            float2 v0, v1;
            v0.x = sx0 * (facc[mf][nf][0] - zx0 * ws0);
            v0.y = sx0 * (facc[mf][nf][1] - zx0 * ws1);
            v1.x = sx1 * (facc[mf][nf][2] - zx1 * ws0);
            v1.y = sx1 * (facc[mf][nf][3] - zx1 * ws1);
            *(float2*)(row_lo + nf * 8) = v0;
            *(float2*)(row_hi + nf * 8) = v1;
        }
    }
}

// ============================================================
// Launcher
// ============================================================
extern "C" void kernel_launch(void* const* d_in, const int* in_sizes, int n_in,
                              void* d_out, int out_size) {
    const float* x = (const float*)d_in[0];   // [4, 2048, 4096] fp32
    const float* w = (const float*)d_in[1];   // [4096, 4096] fp32
    float* out = (float*)d_out;               // [4, 2048, 4096] fp32

    cudaFuncSetAttribute(gemm_kernel, cudaFuncAttributeMaxDynamicSharedMemorySize, GEMM_SMEM);

    fused_quant_kernel<<<FUSED_BLOCKS, 256>>>(x, w);  // weights + activations together
    wsum_kernel<<<512, 256>>>();                      // 4096 rows / 8 per block
    gemm_kernel<<<dim3(NDIM / TN, MROWS / TM), THREADS, GEMM_SMEM>>>(out);
}

// round 15
// speedup vs baseline: 1.1899x; 1.0022x over previous
#include <cuda_runtime.h>
#include <cstdint>
#include <cstddef>

// ============================================================
// Problem dims (fixed)
// ============================================================
#define MROWS 8192
#define NDIM  4096
#define KDIM  4096
#define KGROUPS 32                   // 4096 / 128 quant groups per row

// GEMM tiling: CTA 128x128, 8 warps (2 M x 4 N), warp tile 64x32  (measured best)
#define TM 128
#define TN 128
#define KB 128                       // K int8 per stage = ONE quant group
#define NKB (KDIM / KB)              // 32
#define NSTAGES 4
#define A_BYTES (TM * 128)           // 16384
#define B_BYTES (TN * 128)           // 16384
#define STAGE_BYTES (A_BYTES + B_BYTES)            // 32768
#define SW_BYTES (KGROUPS * TN * 4)                // 16384 group scales in SMEM
#define GEMM_SMEM (SW_BYTES + NSTAGES * STAGE_BYTES)   // 147456

#define THREADS 256                  // 8 warps

// Fused quant kernel grid split: one weight ROW (32 groups) per wq-block
#define WQ_BLOCKS NDIM               // 4096 rows x 32 groups = 131072 groups
#define AQ_BLOCKS MROWS              // one activation row per block
#define FUSED_BLOCKS (WQ_BLOCKS + AQ_BLOCKS)

// ============================================================
// Scratch (static __device__ — no runtime allocation)
// ============================================================
__device__ signed char g_XQ[(size_t)MROWS * KDIM];   // 32 MB: qx int8 (exact)
__device__ signed char g_WQ[(size_t)NDIM * KDIM];    // 16 MB: wq = (q - z) in [0,15]
__device__ float g_SX[MROWS];                        // activation scale per row
__device__ float g_ZX[MROWS];                        // activation zero per row
__device__ float g_WS[(size_t)NDIM * KGROUPS];       // weight group scale sw[n][g]
__device__ float g_WSUM[NDIM];                       // sum_k w_deq[n][k]

// ============================================================
// PTX helpers (sm_100 baseline ISA — no 'a'-suffix features)
// ============================================================
__device__ __forceinline__ uint32_t smem_u32(const void* p) {
    uint32_t a;
    asm("{ .reg .u64 t; cvta.to.shared.u64 t, %1; cvt.u32.u64 %0, t; }" : "=r"(a) : "l"(p));
    return a;
}

#define CP16(smem_addr, gptr) \
    asm volatile("cp.async.cg.shared.global [%0], [%1], 16;" :: "r"(smem_addr), "l"(gptr) : "memory")
#define CP_COMMIT()  asm volatile("cp.async.commit_group;" ::: "memory")
#define CP_WAIT2()   asm volatile("cp.async.wait_group 2;" ::: "memory")
#define CP_WAIT0()   asm volatile("cp.async.wait_group 0;" ::: "memory")

#define LDSM_X4(r0, r1, r2, r3, addr)                                        \
    asm volatile("ldmatrix.sync.aligned.m8n8.x4.shared.b16 {%0,%1,%2,%3}, [%4];" \
                 : "=r"(r0), "=r"(r1), "=r"(r2), "=r"(r3) : "r"(addr))

#define MMAS8(c, a, b0, b1)                                                  \
    asm volatile("mma.sync.aligned.m16n8k32.row.col.s32.s8.s8.s32 "          \
                 "{%0,%1,%2,%3}, {%4,%5,%6,%7}, {%8,%9}, {%0,%1,%2,%3};"     \
                 : "+r"((c)[0]), "+r"((c)[1]), "+r"((c)[2]), "+r"((c)[3])    \
                 : "r"((a)[0]), "r"((a)[1]), "r"((a)[2]), "r"((a)[3]),       \
                   "r"((b0)), "r"((b1)))

// Stage load: A rows {r0,+32,+64,+96}, B rows same; one 16B chunk/row/thread.
#define LOAD_STAGE(kb)                                                        \
    do {                                                                      \
        const uint32_t so_ = (uint32_t)((kb) & (NSTAGES - 1)) * STAGE_BYTES;  \
        const signed char* pA = gA + (size_t)(kb) * 128;                      \
        const signed char* pB = gB + (size_t)(kb) * 128;                      \
        CP16(smA + so_,            pA);                                       \
        CP16(smA + so_ + 32 * 128, pA + (size_t)32 * KDIM);                   \
        CP16(smA + so_ + 64 * 128, pA + (size_t)64 * KDIM);                   \
        CP16(smA + so_ + 96 * 128, pA + (size_t)96 * KDIM);                   \
        CP16(smB + so_,            pB);                                       \
        CP16(smB + so_ + 32 * 128, pB + (size_t)32 * KDIM);                   \
        CP16(smB + so_ + 64 * 128, pB + (size_t)64 * KDIM);                   \
        CP16(smB + so_ + 96 * 128, pB + (size_t)96 * KDIM);                   \
        CP_COMMIT();                                                          \
    } while (0)

// ============================================================
// Kernel 1 (FUSED): weight row quant (+WSUM in-block) + activation row quant.
//   blocks [0, WQ_BLOCKS):            row n's 32 weight groups (4 per warp)
//                                     + in-block WSUM[n] reduction
//   blocks [WQ_BLOCKS, FUSED_BLOCKS): one activation row per block
// Per-element division replaced by multiply with once-per-group reciprocal.
// ============================================================
__global__ void __launch_bounds__(256) fused_quant_kernel(
    const float* __restrict__ x, const float* __restrict__ w) {
    if (blockIdx.x < WQ_BLOCKS) {
        // ---------------- weight group quant (gs=128, nbit=4, asym) ----------------
        // Block b owns weight row n=b: groups b*32 .. b*32+31.
        int warp  = threadIdx.x >> 5;
        int gbase = blockIdx.x * 32 + warp * 4;   // 4 groups per warp
        int lane  = threadIdx.x & 31;

        float4 f[4];
#pragma unroll
        for (int i = 0; i < 4; i++)
            f[i] = ((const float4*)(w + (size_t)(gbase + i) * 128))[lane];

        float wsum_part = 0.0f;                   // lane 0: sum of this warp's 4 groups
#pragma unroll
        for (int i = 0; i < 4; i++) {
            int g = gbase + i;
            float v[4] = {f[i].x, f[i].y, f[i].z, f[i].w};
            float mn = fminf(fminf(v[0], v[1]), fminf(v[2], v[3]));
            float mx = fmaxf(fmaxf(v[0], v[1]), fmaxf(v[2], v[3]));
#pragma unroll
            for (int off = 16; off > 0; off >>= 1) {
                mn = fminf(mn, __shfl_xor_sync(0xffffffffu, mn, off));
                mx = fmaxf(mx, __shfl_xor_sync(0xffffffffu, mx, off));
            }
            float sc = __fdiv_rn(mx - mn, 15.0f);
            if (!(sc > 0.0f)) sc = 1.0f;
            float z   = -8.0f - rintf(__fdiv_rn(mn, sc));   // once per group: exact
            float inv = __fdiv_rn(1.0f, sc);                // once per group

            float gsum = 0.0f;
            signed char o[4];
#pragma unroll
            for (int j = 0; j < 4; j++) {
                float q = rintf(v[j] * inv) + z;
                q = fminf(fmaxf(q, -8.0f), 7.0f);
                float wq = q - z;             // exact small integer in [0,15]
                gsum += wq;
                o[j] = (signed char)__float2int_rn(wq);
            }
            ((char4*)(g_WQ + (size_t)g * 128))[lane] = make_char4(o[0], o[1], o[2], o[3]);
#pragma unroll
            for (int off = 16; off > 0; off >>= 1)
                gsum += __shfl_xor_sync(0xffffffffu, gsum, off);
            if (lane == 0) {
                g_WS[g] = sc;
                wsum_part += sc * gsum;       // accumulate sw * sum(wq) per group
            }
        }

        // In-block WSUM[n] reduction across 8 warps (replaces wsum_kernel)
        __shared__ float warp_wsum[8];
        if (lane == 0) warp_wsum[warp] = wsum_part;
        __syncthreads();
        if (threadIdx.x == 0) {
            float s = warp_wsum[0];
#pragma unroll
            for (int i = 1; i < 8; i++) s += warp_wsum[i];
            g_WSUM[blockIdx.x] = s;
        }
    } else {
        // ---------------- activation dynamic per-row int8 quant ----------------
        int row = blockIdx.x - WQ_BLOCKS;
        int tid = threadIdx.x;
        const float4* xr4 = (const float4*)(x + (size_t)row * KDIM);

        float vals[16];
        float mn = 3.4e38f, mx = -3.4e38f;
#pragma unroll
        for (int j = 0; j < 4; j++) {
            float4 f = xr4[tid + j * 256];
            vals[4 * j + 0] = f.x; vals[4 * j + 1] = f.y;
            vals[4 * j + 2] = f.z; vals[4 * j + 3] = f.w;
            mn = fminf(mn, fminf(fminf(f.x, f.y), fminf(f.z, f.w)));
            mx = fmaxf(mx, fmaxf(fmaxf(f.x, f.y), fmaxf(f.z, f.w)));
        }
#pragma unroll
        for (int off = 16; off > 0; off >>= 1) {
            mn = fminf(mn, __shfl_xor_sync(0xffffffffu, mn, off));
            mx = fmaxf(mx, __shfl_xor_sync(0xffffffffu, mx, off));
        }
        __shared__ float smin[8], smax[8];
        __shared__ float s_z, s_inv;
        if ((tid & 31) == 0) { smin[tid >> 5] = mn; smax[tid >> 5] = mx; }
        __syncthreads();
        if (tid == 0) {
            float rmn = smin[0], rmx = smax[0];
#pragma unroll
            for (int i = 1; i < 8; i++) { rmn = fminf(rmn, smin[i]); rmx = fmaxf(rmx, smax[i]); }
            float sc = __fdiv_rn(rmx - rmn, 255.0f);
            if (!(sc > 0.0f)) sc = 1.0f;
            float z = -128.0f - rintf(__fdiv_rn(rmn, sc));  // once per row: exact
            s_z = z;
            s_inv = __fdiv_rn(1.0f, sc);                    // once per row
            g_SX[row] = sc;
            g_ZX[row] = z;
        }
        __syncthreads();
        float inv = s_inv, z = s_z;
        char4* outp4 = (char4*)(g_XQ + (size_t)row * KDIM);
#pragma unroll
        for (int j = 0; j < 4; j++) {
            signed char o[4];
#pragma unroll
            for (int e = 0; e < 4; e++) {
                float q = rintf(vals[4 * j + e] * inv) + z;
                q = fminf(fmaxf(q, -128.0f), 127.0f);
                o[e] = (signed char)__float2int_rn(q);
            }
            outp4[tid + j * 256] = make_char4(o[0], o[1], o[2], o[3]);
        }
    }
}

// ============================================================
// Kernel 2: int8 IMMA GEMM — measured-best configuration (527.5 us)
// CTA 128x128, 8 warps (2 M x 4 N), warp tile 64x32; K-stage = 1 group.
// 4-stage cp.async ring; uniform tail commits (provable stage completion).
//   y[m,n] = sx_m * ( sum_g sw[n,g]*S1_g[m,n] ) - sx_m*zx_m*WSUM[n]
//   S1_g exact int32 (|.| < 2^22 -> exact I2F).
// ============================================================
__global__ void __launch_bounds__(THREADS, 1)
gemm_kernel(float* __restrict__ out) {
    extern __shared__ char smem[];
    const uint32_t swbase = smem_u32(smem);          // [32 g][128 n] fp32 = 16 KB
    const uint32_t tiles  = swbase + SW_BYTES;

    const int tid  = threadIdx.x;
    const int wid  = tid >> 5;
    const int lane = tid & 31;
    const int wm   = wid & 1;        // 0..1  (M)
    const int wn   = wid >> 1;       // 0..3  (N)

    const int m0 = blockIdx.y * TM;
    const int n0 = blockIdx.x * TN;

    // ---------- producer addressing ----------
    const int  r0  = tid >> 3;       // 0..31
    const int  c   = tid & 7;        // 16B chunk within 128B row
    const uint32_t swz = (uint32_t)(((c ^ (r0 & 7)) & 7) * 16);

    const signed char* gA = g_XQ + (size_t)(m0 + r0) * KDIM + c * 16;
    const signed char* gB = g_WQ + (size_t)(n0 + r0) * KDIM + c * 16;
    const uint32_t smA = tiles + (uint32_t)r0 * 128 + swz;
    const uint32_t smB = tiles + A_BYTES + (uint32_t)r0 * 128 + swz;

    // ---------- prologue: 3 stages in flight (issued FIRST so the scale
    // staging LDGs below overlap with cp.async flight time) ----------
    LOAD_STAGE(0);
    LOAD_STAGE(1);
    LOAD_STAGE(2);

    // ---------- stage the group scales: sw_s[g][n] = g_WS[(n0+n)*32 + g] ----------
    for (int idx = tid; idx < KGROUPS * TN; idx += THREADS) {
        int n = idx >> 5;            // g contiguous in gmem -> coalesced LDG
        int g = idx & 31;
        ((float*)smem)[g * TN + n] = g_WS[(size_t)(n0 + n) * KGROUPS + g];
    }

    // ---------- consumer (ldmatrix) addressing ----------
    const uint32_t xr = (uint32_t)((lane & 7) * 16);
    // A x4 (m16 x k32): rows wm*64 + mf*16 + (lane&7) + ((lane>>3)&1)*8
    const uint32_t adA0 = tiles +
        (uint32_t)(wm * 64 + (lane & 7) + ((lane >> 3) & 1) * 8) * 128;
    const uint32_t ach = (uint32_t)((lane >> 4) * 16);
    // B x4 (2 n-frags x k32): rows wn*32 + g*16 + (lane&7) + (lane>>4)*8
    const uint32_t adB0 = tiles + A_BYTES +
        (uint32_t)(wn * 32 + (lane & 7) + (lane >> 4) * 8) * 128;
    const uint32_t bch = (uint32_t)(((lane >> 3) & 1) * 16);

    float facc[4][4][4];
#pragma unroll
    for (int i = 0; i < 4; i++)
#pragma unroll
        for (int j = 0; j < 4; j++)
#pragma unroll
            for (int q = 0; q < 4; q++) facc[i][j][q] = 0.0f;

    const int ncol2 = (lane & 3) * 2;

    // ---------- main loop: one quant group per iteration ----------
    for (int kb = 0; kb < NKB; kb++) {
        // Commits issued before this wait: 3 + kb (uniform, incl. tail).
        // wait<=2 pending => >= kb+1 complete => stage kb's commit done.
        CP_WAIT2();
        __syncthreads();

        // next stage's global loads; empty commit in tail keeps count uniform
        if (kb + 3 < NKB) { LOAD_STAGE(kb + 3); } else { CP_COMMIT(); }

        const uint32_t so = (uint32_t)(kb & (NSTAGES - 1)) * STAGE_BYTES;

        // group scales for this thread's 8 n-columns
        float swr[8];
        {
            const float* swp = (const float*)smem + (size_t)kb * TN + wn * 32 + ncol2;
#pragma unroll
            for (int nf = 0; nf < 4; nf++) {
                float2 s2 = *(const float2*)(swp + nf * 8);
                swr[2 * nf]     = s2.x;
                swr[2 * nf + 1] = s2.y;
            }
        }

        // B fragments for all 4 k-steps
        uint32_t bu[4][8];
#pragma unroll
        for (int ks = 0; ks < 4; ks++) {
            const uint32_t kc = (uint32_t)(ks * 32);
            LDSM_X4(bu[ks][0], bu[ks][1], bu[ks][2], bu[ks][3],
                    adB0 + so + ((kc + bch) ^ xr));
            LDSM_X4(bu[ks][4], bu[ks][5], bu[ks][6], bu[ks][7],
                    adB0 + 2048 + so + ((kc + bch) ^ xr));
        }

#pragma unroll
        for (int mf = 0; mf < 4; mf++) {
            int ic[4][4];
#pragma unroll
            for (int nf = 0; nf < 4; nf++)
#pragma unroll
                for (int q = 0; q < 4; q++) ic[nf][q] = 0;

#pragma unroll
            for (int ks = 0; ks < 4; ks++) {
                const uint32_t kc = (uint32_t)(ks * 32);
                uint32_t a[4];
                LDSM_X4(a[0], a[1], a[2], a[3],
                        adA0 + (uint32_t)mf * 2048 + so + ((kc + ach) ^ xr));
#pragma unroll
                for (int nf = 0; nf < 4; nf++)
                    MMAS8(ic[nf], a, bu[ks][2 * nf], bu[ks][2 * nf + 1]);
            }
            // fold group: facc += sw * S1  (I2F exact: |S1| < 2^22)
#pragma unroll
            for (int nf = 0; nf < 4; nf++) {
                facc[mf][nf][0] += __int2float_rn(ic[nf][0]) * swr[2 * nf];
                facc[mf][nf][1] += __int2float_rn(ic[nf][1]) * swr[2 * nf + 1];
                facc[mf][nf][2] += __int2float_rn(ic[nf][2]) * swr[2 * nf];
                facc[mf][nf][3] += __int2float_rn(ic[nf][3]) * swr[2 * nf + 1];
            }
        }
        __syncthreads();
    }
    CP_WAIT0();

    // ---------- epilogue: y = sx*(facc - zx*WSUM[n]) ----------
#pragma unroll
    for (int mf = 0; mf < 4; mf++) {
        const int m_lo = m0 + wm * 64 + mf * 16 + (lane >> 2);
        const int m_hi = m_lo + 8;
        const float sx0 = g_SX[m_lo], zx0 = g_ZX[m_lo];
        const float sx1 = g_SX[m_hi], zx1 = g_ZX[m_hi];
        float* row_lo = out + (size_t)m_lo * NDIM + n0 + wn * 32 + ncol2;
        float* row_hi = out + (size_t)m_hi * NDIM + n0 + wn * 32 + ncol2;
#pragma unroll
        for (int nf = 0; nf < 4; nf++) {
            const int ng = n0 + wn * 32 + nf * 8 + ncol2;
            const float ws0 = g_WSUM[ng];
            const float ws1 = g_WSUM[ng + 1];
            float2 v0, v1;
            v0.x = sx0 * (facc[mf][nf][0] - zx0 * ws0);
            v0.y = sx0 * (facc[mf][nf][1] - zx0 * ws1);
            v1.x = sx1 * (facc[mf][nf][2] - zx1 * ws0);
            v1.y = sx1 * (facc[mf][nf][3] - zx1 * ws1);
            *(float2*)(row_lo + nf * 8) = v0;
            *(float2*)(row_hi + nf * 8) = v1;
        }
    }
}

// ============================================================
// Launcher
// ============================================================
extern "C" void kernel_launch(void* const* d_in, const int* in_sizes, int n_in,
                              void* d_out, int out_size) {
    const float* x = (const float*)d_in[0];   // [4, 2048, 4096] fp32
    const float* w = (const float*)d_in[1];   // [4096, 4096] fp32
    float* out = (float*)d_out;               // [4, 2048, 4096] fp32

    cudaFuncSetAttribute(gemm_kernel, cudaFuncAttributeMaxDynamicSharedMemorySize, GEMM_SMEM);

    fused_quant_kernel<<<FUSED_BLOCKS, 256>>>(x, w);  // weights (+WSUM) + activations
    gemm_kernel<<<dim3(NDIM / TN, MROWS / TM), THREADS, GEMM_SMEM>>>(out);
}

// round 16
// speedup vs baseline: 1.1947x; 1.0040x over previous
#include <cuda_runtime.h>
#include <cstdint>
#include <cstddef>

// ============================================================
// Problem dims (fixed)
// ============================================================
#define MROWS 8192
#define NDIM  4096
#define KDIM  4096
#define KGROUPS 32                   // 4096 / 128 quant groups per row

// GEMM tiling: CTA 128x128, 8 warps (2 M x 4 N), warp tile 64x32  (measured best)
#define TM 128
#define TN 128
#define KB 128                       // K int8 per stage = ONE quant group
#define NKB (KDIM / KB)              // 32
#define NSTAGES 4
#define A_BYTES (TM * 128)           // 16384
#define B_BYTES (TN * 128)           // 16384
#define STAGE_BYTES (A_BYTES + B_BYTES)            // 32768
#define SW_BYTES (KGROUPS * TN * 4)                // 16384 group scales in SMEM
#define GEMM_SMEM (SW_BYTES + NSTAGES * STAGE_BYTES)   // 147456

#define THREADS 256                  // 8 warps

// Fused quant kernel grid split: one weight ROW (32 groups) per wq-block
#define WQ_BLOCKS NDIM               // 4096 rows x 32 groups = 131072 groups
#define AQ_BLOCKS MROWS              // one activation row per block
#define FUSED_BLOCKS (WQ_BLOCKS + AQ_BLOCKS)

// ============================================================
// Scratch (static __device__ — no runtime allocation)
// ============================================================
__device__ signed char g_XQ[(size_t)MROWS * KDIM];   // 32 MB: qx int8 (exact)
__device__ signed char g_WQ[(size_t)NDIM * KDIM];    // 16 MB: wq = (q - z) in [0,15]
__device__ float g_SX[MROWS];                        // activation scale per row
__device__ float g_ZX[MROWS];                        // activation zero per row
__device__ float g_WS[(size_t)NDIM * KGROUPS];       // weight group scale sw[n][g]
__device__ float g_WSUM[NDIM];                       // sum_k w_deq[n][k]

// ============================================================
// PTX helpers (sm_100 baseline ISA — no 'a'-suffix features)
// ============================================================
__device__ __forceinline__ uint32_t smem_u32(const void* p) {
    uint32_t a;
    asm("{ .reg .u64 t; cvta.to.shared.u64 t, %1; cvt.u32.u64 %0, t; }" : "=r"(a) : "l"(p));
    return a;
}

#define CP16(smem_addr, gptr) \
    asm volatile("cp.async.cg.shared.global [%0], [%1], 16;" :: "r"(smem_addr), "l"(gptr) : "memory")
#define CP_COMMIT()  asm volatile("cp.async.commit_group;" ::: "memory")
#define CP_WAIT2()   asm volatile("cp.async.wait_group 2;" ::: "memory")
#define CP_WAIT0()   asm volatile("cp.async.wait_group 0;" ::: "memory")

#define LDSM_X4(r0, r1, r2, r3, addr)                                        \
    asm volatile("ldmatrix.sync.aligned.m8n8.x4.shared.b16 {%0,%1,%2,%3}, [%4];" \
                 : "=r"(r0), "=r"(r1), "=r"(r2), "=r"(r3) : "r"(addr))

#define MMAS8(c, a, b0, b1)                                                  \
    asm volatile("mma.sync.aligned.m16n8k32.row.col.s32.s8.s8.s32 "          \
                 "{%0,%1,%2,%3}, {%4,%5,%6,%7}, {%8,%9}, {%0,%1,%2,%3};"     \
                 : "+r"((c)[0]), "+r"((c)[1]), "+r"((c)[2]), "+r"((c)[3])    \
                 : "r"((a)[0]), "r"((a)[1]), "r"((a)[2]), "r"((a)[3]),       \
                   "r"((b0)), "r"((b1)))

// Stage load: A rows {r0,+32,+64,+96}, B rows same; one 16B chunk/row/thread.
#define LOAD_STAGE(kb)                                                        \
    do {                                                                      \
        const uint32_t so_ = (uint32_t)((kb) & (NSTAGES - 1)) * STAGE_BYTES;  \
        const signed char* pA = gA + (size_t)(kb) * 128;                      \
        const signed char* pB = gB + (size_t)(kb) * 128;                      \
        CP16(smA + so_,            pA);                                       \
        CP16(smA + so_ + 32 * 128, pA + (size_t)32 * KDIM);                   \
        CP16(smA + so_ + 64 * 128, pA + (size_t)64 * KDIM);                   \
        CP16(smA + so_ + 96 * 128, pA + (size_t)96 * KDIM);                   \
        CP16(smB + so_,            pB);                                       \
        CP16(smB + so_ + 32 * 128, pB + (size_t)32 * KDIM);                   \
        CP16(smB + so_ + 64 * 128, pB + (size_t)64 * KDIM);                   \
        CP16(smB + so_ + 96 * 128, pB + (size_t)96 * KDIM);                   \
        CP_COMMIT();                                                          \
    } while (0)

// ============================================================
// Kernel 1 (FUSED): weight row quant (+WSUM in-block) + activation row quant.
//   blocks [0, WQ_BLOCKS):            row n's 32 weight groups (4 per warp)
//                                     + in-block WSUM[n] reduction
//   blocks [WQ_BLOCKS, FUSED_BLOCKS): one activation row per block
// Inner loop: F2I.rn + integer add/clamp (bit-identical to the float
// rintf/fadd/fminf/fmaxf chain, but shorter and on the ALU pipe).
// ============================================================
__global__ void __launch_bounds__(256) fused_quant_kernel(
    const float* __restrict__ x, const float* __restrict__ w) {
    if (blockIdx.x < WQ_BLOCKS) {
        // ---------------- weight group quant (gs=128, nbit=4, asym) ----------------
        // Block b owns weight row n=b: groups b*32 .. b*32+31.
        int warp  = threadIdx.x >> 5;
        int gbase = blockIdx.x * 32 + warp * 4;   // 4 groups per warp
        int lane  = threadIdx.x & 31;

        float4 f[4];
#pragma unroll
        for (int i = 0; i < 4; i++)
            f[i] = ((const float4*)(w + (size_t)(gbase + i) * 128))[lane];

        float wsum_part = 0.0f;                   // lane 0: sum of this warp's 4 groups
#pragma unroll
        for (int i = 0; i < 4; i++) {
            int g = gbase + i;
            float v[4] = {f[i].x, f[i].y, f[i].z, f[i].w};
            float mn = fminf(fminf(v[0], v[1]), fminf(v[2], v[3]));
            float mx = fmaxf(fmaxf(v[0], v[1]), fmaxf(v[2], v[3]));
#pragma unroll
            for (int off = 16; off > 0; off >>= 1) {
                mn = fminf(mn, __shfl_xor_sync(0xffffffffu, mn, off));
                mx = fmaxf(mx, __shfl_xor_sync(0xffffffffu, mx, off));
            }
            float sc = __fdiv_rn(mx - mn, 15.0f);
            if (!(sc > 0.0f)) sc = 1.0f;
            float zf  = -8.0f - rintf(__fdiv_rn(mn, sc));   // once per group: exact
            float inv = __fdiv_rn(1.0f, sc);                // once per group
            int   zi  = (int)zf;                            // integer-valued

            int gsum_i = 0;
            signed char o[4];
#pragma unroll
            for (int j = 0; j < 4; j++) {
                int q = __float2int_rn(v[j] * inv) + zi;    // rint half-even + exact add
                q = min(max(q, -8), 7);                     // IMNMX (ALU pipe)
                int wq = q - zi;                            // exact integer in [0,15]
                gsum_i += wq;
                o[j] = (signed char)wq;
            }
            ((char4*)(g_WQ + (size_t)g * 128))[lane] = make_char4(o[0], o[1], o[2], o[3]);
#pragma unroll
            for (int off = 16; off > 0; off >>= 1)
                gsum_i += __shfl_xor_sync(0xffffffffu, gsum_i, off);
            if (lane == 0) {
                g_WS[g] = sc;
                wsum_part += sc * (float)gsum_i;  // exact: gsum_i <= 1920 < 2^24
            }
        }

        // In-block WSUM[n] reduction across 8 warps
        __shared__ float warp_wsum[8];
        if (lane == 0) warp_wsum[warp] = wsum_part;
        __syncthreads();
        if (threadIdx.x == 0) {
            float s = warp_wsum[0];
#pragma unroll
            for (int i = 1; i < 8; i++) s += warp_wsum[i];
            g_WSUM[blockIdx.x] = s;
        }
    } else {
        // ---------------- activation dynamic per-row int8 quant ----------------
        int row = blockIdx.x - WQ_BLOCKS;
        int tid = threadIdx.x;
        const float4* xr4 = (const float4*)(x + (size_t)row * KDIM);

        float vals[16];
        float mn = 3.4e38f, mx = -3.4e38f;
#pragma unroll
        for (int j = 0; j < 4; j++) {
            float4 f = xr4[tid + j * 256];
            vals[4 * j + 0] = f.x; vals[4 * j + 1] = f.y;
            vals[4 * j + 2] = f.z; vals[4 * j + 3] = f.w;
            mn = fminf(mn, fminf(fminf(f.x, f.y), fminf(f.z, f.w)));
            mx = fmaxf(mx, fmaxf(fmaxf(f.x, f.y), fmaxf(f.z, f.w)));
        }
#pragma unroll
        for (int off = 16; off > 0; off >>= 1) {
            mn = fminf(mn, __shfl_xor_sync(0xffffffffu, mn, off));
            mx = fmaxf(mx, __shfl_xor_sync(0xffffffffu, mx, off));
        }
        __shared__ float smin[8], smax[8];
        __shared__ float s_inv;
        __shared__ int   s_zi;
        if ((tid & 31) == 0) { smin[tid >> 5] = mn; smax[tid >> 5] = mx; }
        __syncthreads();
        if (tid == 0) {
            float rmn = smin[0], rmx = smax[0];
#pragma unroll
            for (int i = 1; i < 8; i++) { rmn = fminf(rmn, smin[i]); rmx = fmaxf(rmx, smax[i]); }
            float sc = __fdiv_rn(rmx - rmn, 255.0f);
            if (!(sc > 0.0f)) sc = 1.0f;
            float zf = -128.0f - rintf(__fdiv_rn(rmn, sc)); // once per row: exact
            s_zi  = (int)zf;
            s_inv = __fdiv_rn(1.0f, sc);                    // once per row
            g_SX[row] = sc;
            g_ZX[row] = zf;
        }
        __syncthreads();
        float inv = s_inv;
        int   zi  = s_zi;
        char4* outp4 = (char4*)(g_XQ + (size_t)row * KDIM);
#pragma unroll
        for (int j = 0; j < 4; j++) {
            signed char o[4];
#pragma unroll
            for (int e = 0; e < 4; e++) {
                int q = __float2int_rn(vals[4 * j + e] * inv) + zi;
                q = min(max(q, -128), 127);                 // IMNMX (ALU pipe)
                o[e] = (signed char)q;
            }
            outp4[tid + j * 256] = make_char4(o[0], o[1], o[2], o[3]);
        }
    }
}

// ============================================================
// Kernel 2: int8 IMMA GEMM — measured-best configuration (~530 us wall)
// CTA 128x128, 8 warps (2 M x 4 N), warp tile 64x32; K-stage = 1 group.
// 4-stage cp.async ring; uniform tail commits (provable stage completion).
//   y[m,n] = sx_m * ( sum_g sw[n,g]*S1_g[m,n] ) - sx_m*zx_m*WSUM[n]
//   S1_g exact int32 (|.| < 2^22 -> exact I2F).
// ============================================================
__global__ void __launch_bounds__(THREADS, 1)
gemm_kernel(float* __restrict__ out) {
    extern __shared__ char smem[];
    const uint32_t swbase = smem_u32(smem);          // [32 g][128 n] fp32 = 16 KB
    const uint32_t tiles  = swbase + SW_BYTES;

    const int tid  = threadIdx.x;
    const int wid  = tid >> 5;
    const int lane = tid & 31;
    const int wm   = wid & 1;        // 0..1  (M)
    const int wn   = wid >> 1;       // 0..3  (N)

    const int m0 = blockIdx.y * TM;
    const int n0 = blockIdx.x * TN;

    // ---------- producer addressing ----------
    const int  r0  = tid >> 3;       // 0..31
    const int  c   = tid & 7;        // 16B chunk within 128B row
    const uint32_t swz = (uint32_t)(((c ^ (r0 & 7)) & 7) * 16);

    const signed char* gA = g_XQ + (size_t)(m0 + r0) * KDIM + c * 16;
    const signed char* gB = g_WQ + (size_t)(n0 + r0) * KDIM + c * 16;
    const uint32_t smA = tiles + (uint32_t)r0 * 128 + swz;
    const uint32_t smB = tiles + A_BYTES + (uint32_t)r0 * 128 + swz;

    // ---------- prologue: 3 stages in flight (issued FIRST so the scale
    // staging LDGs below overlap with cp.async flight time) ----------
    LOAD_STAGE(0);
    LOAD_STAGE(1);
    LOAD_STAGE(2);

    // ---------- stage the group scales: sw_s[g][n] = g_WS[(n0+n)*32 + g] ----------
    for (int idx = tid; idx < KGROUPS * TN; idx += THREADS) {
        int n = idx >> 5;            // g contiguous in gmem -> coalesced LDG
        int g = idx & 31;
        ((float*)smem)[g * TN + n] = g_WS[(size_t)(n0 + n) * KGROUPS + g];
    }

    // ---------- consumer (ldmatrix) addressing ----------
    const uint32_t xr = (uint32_t)((lane & 7) * 16);
    // A x4 (m16 x k32): rows wm*64 + mf*16 + (lane&7) + ((lane>>3)&1)*8
    const uint32_t adA0 = tiles +
        (uint32_t)(wm * 64 + (lane & 7) + ((lane >> 3) & 1) * 8) * 128;
    const uint32_t ach = (uint32_t)((lane >> 4) * 16);
    // B x4 (2 n-frags x k32): rows wn*32 + g*16 + (lane&7) + (lane>>4)*8
    const uint32_t adB0 = tiles + A_BYTES +
        (uint32_t)(wn * 32 + (lane & 7) + (lane >> 4) * 8) * 128;
    const uint32_t bch = (uint32_t)(((lane >> 3) & 1) * 16);

    float facc[4][4][4];
#pragma unroll
    for (int i = 0; i < 4; i++)
#pragma unroll
        for (int j = 0; j < 4; j++)
#pragma unroll
            for (int q = 0; q < 4; q++) facc[i][j][q] = 0.0f;

    const int ncol2 = (lane & 3) * 2;

    // ---------- main loop: one quant group per iteration ----------
    for (int kb = 0; kb < NKB; kb++) {
        // Commits issued before this wait: 3 + kb (uniform, incl. tail).
        // wait<=2 pending => >= kb+1 complete => stage kb's commit done.
        CP_WAIT2();
        __syncthreads();

        // next stage's global loads; empty commit in tail keeps count uniform
        if (kb + 3 < NKB) { LOAD_STAGE(kb + 3); } else { CP_COMMIT(); }

        const uint32_t so = (uint32_t)(kb & (NSTAGES - 1)) * STAGE_BYTES;

        // group scales for this thread's 8 n-columns
        float swr[8];
        {
            const float* swp = (const float*)smem + (size_t)kb * TN + wn * 32 + ncol2;
#pragma unroll
            for (int nf = 0; nf < 4; nf++) {
                float2 s2 = *(const float2*)(swp + nf * 8);
                swr[2 * nf]     = s2.x;
                swr[2 * nf + 1] = s2.y;
            }
        }

        // B fragments for all 4 k-steps
        uint32_t bu[4][8];
#pragma unroll
        for (int ks = 0; ks < 4; ks++) {
            const uint32_t kc = (uint32_t)(ks * 32);
            LDSM_X4(bu[ks][0], bu[ks][1], bu[ks][2], bu[ks][3],
                    adB0 + so + ((kc + bch) ^ xr));
            LDSM_X4(bu[ks][4], bu[ks][5], bu[ks][6], bu[ks][7],
                    adB0 + 2048 + so + ((kc + bch) ^ xr));
        }

#pragma unroll
        for (int mf = 0; mf < 4; mf++) {
            int ic[4][4];
#pragma unroll
            for (int nf = 0; nf < 4; nf++)
#pragma unroll
                for (int q = 0; q < 4; q++) ic[nf][q] = 0;

#pragma unroll
            for (int ks = 0; ks < 4; ks++) {
                const uint32_t kc = (uint32_t)(ks * 32);
                uint32_t a[4];
                LDSM_X4(a[0], a[1], a[2], a[3],
                        adA0 + (uint32_t)mf * 2048 + so + ((kc + ach) ^ xr));
#pragma unroll
                for (int nf = 0; nf < 4; nf++)
                    MMAS8(ic[nf], a, bu[ks][2 * nf], bu[ks][2 * nf + 1]);
            }
            // fold group: facc += sw * S1  (I2F exact: |S1| < 2^22)
#pragma unroll
            for (int nf = 0; nf < 4; nf++) {
                facc[mf][nf][0] += __int2float_rn(ic[nf][0]) * swr[2 * nf];
                facc[mf][nf][1] += __int2float_rn(ic[nf][1]) * swr[2 * nf + 1];
                facc[mf][nf][2] += __int2float_rn(ic[nf][2]) * swr[2 * nf];
                facc[mf][nf][3] += __int2float_rn(ic[nf][3]) * swr[2 * nf + 1];
            }
        }
        __syncthreads();
    }
    CP_WAIT0();

    // ---------- epilogue: y = sx*(facc - zx*WSUM[n]) ----------
#pragma unroll
    for (int mf = 0; mf < 4; mf++) {
        const int m_lo = m0 + wm * 64 + mf * 16 + (lane >> 2);
        const int m_hi = m_lo + 8;
        const float sx0 = g_SX[m_lo], zx0 = g_ZX[m_lo];
        const float sx1 = g_SX[m_hi], zx1 = g_ZX[m_hi];
        float* row_lo = out + (size_t)m_lo * NDIM + n0 + wn * 32 + ncol2;
        float* row_hi = out + (size_t)m_hi * NDIM + n0 + wn * 32 + ncol2;
#pragma unroll
        for (int nf = 0; nf < 4; nf++) {
            const int ng = n0 + wn * 32 + nf * 8 + ncol2;
            const float ws0 = g_WSUM[ng];
            const float ws1 = g_WSUM[ng + 1];
            float2 v0, v1;
            v0.x = sx0 * (facc[mf][nf][0] - zx0 * ws0);
            v0.y = sx0 * (facc[mf][nf][1] - zx0 * ws1);
            v1.x = sx1 * (facc[mf][nf][2] - zx1 * ws0);
            v1.y = sx1 * (facc[mf][nf][3] - zx1 * ws1);
            *(float2*)(row_lo + nf * 8) = v0;
            *(float2*)(row_hi + nf * 8) = v1;
        }
    }
}

// ============================================================
// Launcher
// ============================================================
extern "C" void kernel_launch(void* const* d_in, const int* in_sizes, int n_in,
                              void* d_out, int out_size) {
    const float* x = (const float*)d_in[0];   // [4, 2048, 4096] fp32
    const float* w = (const float*)d_in[1];   // [4096, 4096] fp32
    float* out = (float*)d_out;               // [4, 2048, 4096] fp32

    cudaFuncSetAttribute(gemm_kernel, cudaFuncAttributeMaxDynamicSharedMemorySize, GEMM_SMEM);

    fused_quant_kernel<<<FUSED_BLOCKS, 256>>>(x, w);  // weights (+WSUM) + activations
    gemm_kernel<<<dim3(NDIM / TN, MROWS / TM), THREADS, GEMM_SMEM>>>(out);
}

// round 17
// speedup vs baseline: 1.2157x; 1.0176x over previous
#include <cuda_runtime.h>
#include <cstdint>
#include <cstddef>

// ============================================================
// Problem dims (fixed)
// ============================================================
#define MROWS 8192
#define NDIM  4096
#define KDIM  4096
#define KGROUPS 32                   // 4096 / 128 quant groups per row

// GEMM tiling: CTA 128x128, 8 warps (2 M x 4 N), warp tile 64x32  (measured best)
#define TM 128
#define TN 128
#define KB 128                       // K int8 per stage = ONE quant group
#define NKB (KDIM / KB)              // 32
#define NSTAGES 4
#define A_BYTES (TM * 128)           // 16384
#define B_BYTES (TN * 128)           // 16384
#define STAGE_BYTES (A_BYTES + B_BYTES)            // 32768
#define SW_BYTES (KGROUPS * TN * 4)                // 16384 group scales in SMEM
#define GEMM_SMEM (SW_BYTES + NSTAGES * STAGE_BYTES)   // 147456

#define THREADS 256                  // 8 warps

// Fused quant kernel grid split: one weight ROW (32 groups) per wq-block
#define WQ_BLOCKS NDIM               // 4096 rows x 32 groups = 131072 groups
#define AQ_BLOCKS MROWS              // one activation row per block
#define FUSED_BLOCKS (WQ_BLOCKS + AQ_BLOCKS)

// ============================================================
// Scratch (static __device__ — no runtime allocation)
// ============================================================
__device__ signed char g_XQ[(size_t)MROWS * KDIM];   // 32 MB: qx int8 (exact)
__device__ signed char g_WQ[(size_t)NDIM * KDIM];    // 16 MB: wq = (q - z) in [0,15]
__device__ float g_SX[MROWS];                        // activation scale per row
__device__ float g_ZX[MROWS];                        // activation zero per row
__device__ float g_WS[(size_t)NDIM * KGROUPS];       // weight group scale sw[n][g]
__device__ float g_WSUM[NDIM];                       // sum_k w_deq[n][k]

// ============================================================
// PTX helpers (sm_100 baseline ISA — no 'a'-suffix features)
// ============================================================
__device__ __forceinline__ uint32_t smem_u32(const void* p) {
    uint32_t a;
    asm("{ .reg .u64 t; cvta.to.shared.u64 t, %1; cvt.u32.u64 %0, t; }" : "=r"(a) : "l"(p));
    return a;
}

#define CP16(smem_addr, gptr) \
    asm volatile("cp.async.cg.shared.global [%0], [%1], 16;" :: "r"(smem_addr), "l"(gptr) : "memory")
#define CP_COMMIT()  asm volatile("cp.async.commit_group;" ::: "memory")
#define CP_WAIT2()   asm volatile("cp.async.wait_group 2;" ::: "memory")
#define CP_WAIT0()   asm volatile("cp.async.wait_group 0;" ::: "memory")

#define LDSM_X4(r0, r1, r2, r3, addr)                                        \
    asm volatile("ldmatrix.sync.aligned.m8n8.x4.shared.b16 {%0,%1,%2,%3}, [%4];" \
                 : "=r"(r0), "=r"(r1), "=r"(r2), "=r"(r3) : "r"(addr))

#define MMAS8(c, a, b0, b1)                                                  \
    asm volatile("mma.sync.aligned.m16n8k32.row.col.s32.s8.s8.s32 "          \
                 "{%0,%1,%2,%3}, {%4,%5,%6,%7}, {%8,%9}, {%0,%1,%2,%3};"     \
                 : "+r"((c)[0]), "+r"((c)[1]), "+r"((c)[2]), "+r"((c)[3])    \
                 : "r"((a)[0]), "r"((a)[1]), "r"((a)[2]), "r"((a)[3]),       \
                   "r"((b0)), "r"((b1)))

// Stage load: A rows {r0,+32,+64,+96}, B rows same; one 16B chunk/row/thread.
#define LOAD_STAGE(kb)                                                        \
    do {                                                                      \
        const uint32_t so_ = (uint32_t)((kb) & (NSTAGES - 1)) * STAGE_BYTES;  \
        const signed char* pA = gA + (size_t)(kb) * 128;                      \
        const signed char* pB = gB + (size_t)(kb) * 128;                      \
        CP16(smA + so_,            pA);                                       \
        CP16(smA + so_ + 32 * 128, pA + (size_t)32 * KDIM);                   \
        CP16(smA + so_ + 64 * 128, pA + (size_t)64 * KDIM);                   \
        CP16(smA + so_ + 96 * 128, pA + (size_t)96 * KDIM);                   \
        CP16(smB + so_,            pB);                                       \
        CP16(smB + so_ + 32 * 128, pB + (size_t)32 * KDIM);                   \
        CP16(smB + so_ + 64 * 128, pB + (size_t)64 * KDIM);                   \
        CP16(smB + so_ + 96 * 128, pB + (size_t)96 * KDIM);                   \
        CP_COMMIT();                                                          \
    } while (0)

// ============================================================
// Kernel 1 (FUSED): weight row quant (+WSUM in-block) + activation row quant.
//   blocks [0, WQ_BLOCKS):            row n's 32 weight groups (4 per warp)
//                                     + in-block WSUM[n] reduction
//   blocks [WQ_BLOCKS, FUSED_BLOCKS): one activation row per block
// Inner loop: F2I.rn + integer add/clamp (bit-identical to the float chain).
// ============================================================
__global__ void __launch_bounds__(256) fused_quant_kernel(
    const float* __restrict__ x, const float* __restrict__ w) {
    if (blockIdx.x < WQ_BLOCKS) {
        // ---------------- weight group quant (gs=128, nbit=4, asym) ----------------
        int warp  = threadIdx.x >> 5;
        int gbase = blockIdx.x * 32 + warp * 4;   // 4 groups per warp
        int lane  = threadIdx.x & 31;

        float4 f[4];
#pragma unroll
        for (int i = 0; i < 4; i++)
            f[i] = ((const float4*)(w + (size_t)(gbase + i) * 128))[lane];

        float wsum_part = 0.0f;                   // lane 0: sum of this warp's 4 groups
#pragma unroll
        for (int i = 0; i < 4; i++) {
            int g = gbase + i;
            float v[4] = {f[i].x, f[i].y, f[i].z, f[i].w};
            float mn = fminf(fminf(v[0], v[1]), fminf(v[2], v[3]));
            float mx = fmaxf(fmaxf(v[0], v[1]), fmaxf(v[2], v[3]));
#pragma unroll
            for (int off = 16; off > 0; off >>= 1) {
                mn = fminf(mn, __shfl_xor_sync(0xffffffffu, mn, off));
                mx = fmaxf(mx, __shfl_xor_sync(0xffffffffu, mx, off));
            }
            float sc = __fdiv_rn(mx - mn, 15.0f);
            if (!(sc > 0.0f)) sc = 1.0f;
            float zf  = -8.0f - rintf(__fdiv_rn(mn, sc));   // once per group: exact
            float inv = __fdiv_rn(1.0f, sc);                // once per group
            int   zi  = (int)zf;                            // integer-valued

            int gsum_i = 0;
            signed char o[4];
#pragma unroll
            for (int j = 0; j < 4; j++) {
                int q = __float2int_rn(v[j] * inv) + zi;    // rint half-even + exact add
                q = min(max(q, -8), 7);                     // IMNMX (ALU pipe)
                int wq = q - zi;                            // exact integer in [0,15]
                gsum_i += wq;
                o[j] = (signed char)wq;
            }
            ((char4*)(g_WQ + (size_t)g * 128))[lane] = make_char4(o[0], o[1], o[2], o[3]);
#pragma unroll
            for (int off = 16; off > 0; off >>= 1)
                gsum_i += __shfl_xor_sync(0xffffffffu, gsum_i, off);
            if (lane == 0) {
                g_WS[g] = sc;
                wsum_part += sc * (float)gsum_i;  // exact: gsum_i <= 1920 < 2^24
            }
        }

        // In-block WSUM[n] reduction across 8 warps
        __shared__ float warp_wsum[8];
        if (lane == 0) warp_wsum[warp] = wsum_part;
        __syncthreads();
        if (threadIdx.x == 0) {
            float s = warp_wsum[0];
#pragma unroll
            for (int i = 1; i < 8; i++) s += warp_wsum[i];
            g_WSUM[blockIdx.x] = s;
        }
    } else {
        // ---------------- activation dynamic per-row int8 quant ----------------
        int row = blockIdx.x - WQ_BLOCKS;
        int tid = threadIdx.x;
        const float4* xr4 = (const float4*)(x + (size_t)row * KDIM);

        float vals[16];
        float mn = 3.4e38f, mx = -3.4e38f;
#pragma unroll
        for (int j = 0; j < 4; j++) {
            float4 f = xr4[tid + j * 256];
            vals[4 * j + 0] = f.x; vals[4 * j + 1] = f.y;
            vals[4 * j + 2] = f.z; vals[4 * j + 3] = f.w;
            mn = fminf(mn, fminf(fminf(f.x, f.y), fminf(f.z, f.w)));
            mx = fmaxf(mx, fmaxf(fmaxf(f.x, f.y), fmaxf(f.z, f.w)));
        }
#pragma unroll
        for (int off = 16; off > 0; off >>= 1) {
            mn = fminf(mn, __shfl_xor_sync(0xffffffffu, mn, off));
            mx = fmaxf(mx, __shfl_xor_sync(0xffffffffu, mx, off));
        }
        __shared__ float smin[8], smax[8];
        __shared__ float s_inv;
        __shared__ int   s_zi;
        if ((tid & 31) == 0) { smin[tid >> 5] = mn; smax[tid >> 5] = mx; }
        __syncthreads();
        if (tid == 0) {
            float rmn = smin[0], rmx = smax[0];
#pragma unroll
            for (int i = 1; i < 8; i++) { rmn = fminf(rmn, smin[i]); rmx = fmaxf(rmx, smax[i]); }
            float sc = __fdiv_rn(rmx - rmn, 255.0f);
            if (!(sc > 0.0f)) sc = 1.0f;
            float zf = -128.0f - rintf(__fdiv_rn(rmn, sc)); // once per row: exact
            s_zi  = (int)zf;
            s_inv = __fdiv_rn(1.0f, sc);                    // once per row
            g_SX[row] = sc;
            g_ZX[row] = zf;
        }
        __syncthreads();
        float inv = s_inv;
        int   zi  = s_zi;
        char4* outp4 = (char4*)(g_XQ + (size_t)row * KDIM);
#pragma unroll
        for (int j = 0; j < 4; j++) {
            signed char o[4];
#pragma unroll
            for (int e = 0; e < 4; e++) {
                int q = __float2int_rn(vals[4 * j + e] * inv) + zi;
                q = min(max(q, -128), 127);                 // IMNMX (ALU pipe)
                o[e] = (signed char)q;
            }
            outp4[tid + j * 256] = make_char4(o[0], o[1], o[2], o[3]);
        }
    }
}

// ============================================================
// Kernel 2: int8 IMMA GEMM — measured-best config, SINGLE barrier per stage.
// CTA 128x128, 8 warps (2 M x 4 N), warp tile 64x32; K-stage = 1 group.
// 4-stage cp.async ring; uniform tail commits (provable stage completion).
// Bottom __syncthreads removed: writes issued in iter kb target stage
// (kb+3)%4 == (kb-1)%4, last read in iter kb-1; every writer passed the TOP
// barrier of iter kb, ordering it after all iter kb-1 (synchronous ldmatrix)
// reads. A fast warp cannot lap the ring: the next top barrier blocks it.
//   y[m,n] = sx_m * ( sum_g sw[n,g]*S1_g[m,n] ) - sx_m*zx_m*WSUM[n]
// ============================================================
__global__ void __launch_bounds__(THREADS, 1)
gemm_kernel(float* __restrict__ out) {
    extern __shared__ char smem[];
    const uint32_t swbase = smem_u32(smem);          // [32 g][128 n] fp32 = 16 KB
    const uint32_t tiles  = swbase + SW_BYTES;

    const int tid  = threadIdx.x;
    const int wid  = tid >> 5;
    const int lane = tid & 31;
    const int wm   = wid & 1;        // 0..1  (M)
    const int wn   = wid >> 1;       // 0..3  (N)

    const int m0 = blockIdx.y * TM;
    const int n0 = blockIdx.x * TN;

    // ---------- producer addressing ----------
    const int  r0  = tid >> 3;       // 0..31
    const int  c   = tid & 7;        // 16B chunk within 128B row
    const uint32_t swz = (uint32_t)(((c ^ (r0 & 7)) & 7) * 16);

    const signed char* gA = g_XQ + (size_t)(m0 + r0) * KDIM + c * 16;
    const signed char* gB = g_WQ + (size_t)(n0 + r0) * KDIM + c * 16;
    const uint32_t smA = tiles + (uint32_t)r0 * 128 + swz;
    const uint32_t smB = tiles + A_BYTES + (uint32_t)r0 * 128 + swz;

    // ---------- prologue: 3 stages in flight (issued FIRST so the scale
    // staging LDGs below overlap with cp.async flight time) ----------
    LOAD_STAGE(0);
    LOAD_STAGE(1);
    LOAD_STAGE(2);

    // ---------- stage the group scales: sw_s[g][n] = g_WS[(n0+n)*32 + g] ----------
    for (int idx = tid; idx < KGROUPS * TN; idx += THREADS) {
        int n = idx >> 5;            // g contiguous in gmem -> coalesced LDG
        int g = idx & 31;
        ((float*)smem)[g * TN + n] = g_WS[(size_t)(n0 + n) * KGROUPS + g];
    }

    // ---------- consumer (ldmatrix) addressing ----------
    const uint32_t xr = (uint32_t)((lane & 7) * 16);
    // A x4 (m16 x k32): rows wm*64 + mf*16 + (lane&7) + ((lane>>3)&1)*8
    const uint32_t adA0 = tiles +
        (uint32_t)(wm * 64 + (lane & 7) + ((lane >> 3) & 1) * 8) * 128;
    const uint32_t ach = (uint32_t)((lane >> 4) * 16);
    // B x4 (2 n-frags x k32): rows wn*32 + g*16 + (lane&7) + (lane>>4)*8
    const uint32_t adB0 = tiles + A_BYTES +
        (uint32_t)(wn * 32 + (lane & 7) + (lane >> 4) * 8) * 128;
    const uint32_t bch = (uint32_t)(((lane >> 3) & 1) * 16);

    float facc[4][4][4];
#pragma unroll
    for (int i = 0; i < 4; i++)
#pragma unroll
        for (int j = 0; j < 4; j++)
#pragma unroll
            for (int q = 0; q < 4; q++) facc[i][j][q] = 0.0f;

    const int ncol2 = (lane & 3) * 2;

    // ---------- main loop: one quant group per iteration, ONE barrier ----------
    for (int kb = 0; kb < NKB; kb++) {
        // Commits issued before this wait: 3 + kb (uniform, incl. tail).
        // wait<=2 pending => >= kb+1 complete => stage kb's commit done.
        CP_WAIT2();
        __syncthreads();

        // next stage's global loads; empty commit in tail keeps count uniform
        if (kb + 3 < NKB) { LOAD_STAGE(kb + 3); } else { CP_COMMIT(); }

        const uint32_t so = (uint32_t)(kb & (NSTAGES - 1)) * STAGE_BYTES;

        // group scales for this thread's 8 n-columns
        float swr[8];
        {
            const float* swp = (const float*)smem + (size_t)kb * TN + wn * 32 + ncol2;
#pragma unroll
            for (int nf = 0; nf < 4; nf++) {
                float2 s2 = *(const float2*)(swp + nf * 8);
                swr[2 * nf]     = s2.x;
                swr[2 * nf + 1] = s2.y;
            }
        }

        // B fragments for all 4 k-steps
        uint32_t bu[4][8];
#pragma unroll
        for (int ks = 0; ks < 4; ks++) {
            const uint32_t kc = (uint32_t)(ks * 32);
            LDSM_X4(bu[ks][0], bu[ks][1], bu[ks][2], bu[ks][3],
                    adB0 + so + ((kc + bch) ^ xr));
            LDSM_X4(bu[ks][4], bu[ks][5], bu[ks][6], bu[ks][7],
                    adB0 + 2048 + so + ((kc + bch) ^ xr));
        }

#pragma unroll
        for (int mf = 0; mf < 4; mf++) {
            int ic[4][4];
#pragma unroll
            for (int nf = 0; nf < 4; nf++)
#pragma unroll
                for (int q = 0; q < 4; q++) ic[nf][q] = 0;

#pragma unroll
            for (int ks = 0; ks < 4; ks++) {
                const uint32_t kc = (uint32_t)(ks * 32);
                uint32_t a[4];
                LDSM_X4(a[0], a[1], a[2], a[3],
                        adA0 + (uint32_t)mf * 2048 + so + ((kc + ach) ^ xr));
#pragma unroll
                for (int nf = 0; nf < 4; nf++)
                    MMAS8(ic[nf], a, bu[ks][2 * nf], bu[ks][2 * nf + 1]);
            }
            // fold group: facc += sw * S1  (I2F exact: |S1| < 2^22)
#pragma unroll
            for (int nf = 0; nf < 4; nf++) {
                facc[mf][nf][0] += __int2float_rn(ic[nf][0]) * swr[2 * nf];
                facc[mf][nf][1] += __int2float_rn(ic[nf][1]) * swr[2 * nf + 1];
                facc[mf][nf][2] += __int2float_rn(ic[nf][2]) * swr[2 * nf];
                facc[mf][nf][3] += __int2float_rn(ic[nf][3]) * swr[2 * nf + 1];
            }
        }
        // NOTE: no bottom __syncthreads — see kernel header comment for proof.
    }
    CP_WAIT0();

    // ---------- epilogue: y = sx*(facc - zx*WSUM[n]) ----------
#pragma unroll
    for (int mf = 0; mf < 4; mf++) {
        const int m_lo = m0 + wm * 64 + mf * 16 + (lane >> 2);
        const int m_hi = m_lo + 8;
        const float sx0 = g_SX[m_lo], zx0 = g_ZX[m_lo];
        const float sx1 = g_SX[m_hi], zx1 = g_ZX[m_hi];
        float* row_lo = out + (size_t)m_lo * NDIM + n0 + wn * 32 + ncol2;
        float* row_hi = out + (size_t)m_hi * NDIM + n0 + wn * 32 + ncol2;
#pragma unroll
        for (int nf = 0; nf < 4; nf++) {
            const int ng = n0 + wn * 32 + nf * 8 + ncol2;
            const float ws0 = g_WSUM[ng];
            const float ws1 = g_WSUM[ng + 1];
            float2 v0, v1;
            v0.x = sx0 * (facc[mf][nf][0] - zx0 * ws0);
            v0.y = sx0 * (facc[mf][nf][1] - zx0 * ws1);
            v1.x = sx1 * (facc[mf][nf][2] - zx1 * ws0);
            v1.y = sx1 * (facc[mf][nf][3] - zx1 * ws1);
            *(float2*)(row_lo + nf * 8) = v0;
            *(float2*)(row_hi + nf * 8) = v1;
        }
    }
}

// ============================================================
// Launcher
// ============================================================
extern "C" void kernel_launch(void* const* d_in, const int* in_sizes, int n_in,
                              void* d_out, int out_size) {
    const float* x = (const float*)d_in[0];   // [4, 2048, 4096] fp32
    const float* w = (const float*)d_in[1];   // [4096, 4096] fp32
    float* out = (float*)d_out;               // [4, 2048, 4096] fp32

    cudaFuncSetAttribute(gemm_kernel, cudaFuncAttributeMaxDynamicSharedMemorySize, GEMM_SMEM);

    fused_quant_kernel<<<FUSED_BLOCKS, 256>>>(x, w);  // weights (+WSUM) + activations
    gemm_kernel<<<dim3(NDIM / TN, MROWS / TM), THREADS, GEMM_SMEM>>>(out);
}